// round 3
// baseline (speedup 1.0000x reference)
#include <cuda_runtime.h>
#include <math.h>
#include <stdint.h>

#define BSZ   16384
#define DIM   512
#define KNUM  8192
#define NEG_SLOPE 0.01f

// ---- scratch (static device globals) ----
__device__ float g_esq[KNUM];
__device__ float g_H[(size_t)BSZ * DIM];   // fp32 hidden, 32 MB
__device__ int   g_meli1[BSZ], g_meli2[BSZ];
__device__ int   g_logi1[BSZ], g_logi2[BSZ];
__device__ float g_lse[BSZ];
__device__ float g_loss[BSZ], g_match[BSZ];

// ============================================================
// ||e_k||^2
// ============================================================
__global__ void esq_kernel(const float* __restrict__ E) {
    int row  = blockIdx.x * (blockDim.x >> 5) + (threadIdx.x >> 5);
    int lane = threadIdx.x & 31;
    const float* e = E + (size_t)row * DIM;
    float s = 0.f;
    for (int c = lane; c < DIM; c += 32) { float v = e[c]; s = fmaf(v, v, s); }
    #pragma unroll
    for (int o = 16; o; o >>= 1) s += __shfl_xor_sync(0xffffffffu, s, o);
    if (lane == 0) g_esq[row] = s;
}

// ============================================================
// fp32 SIMT GEMM for H (accuracy-critical, small: 17 GFLOP)
// ============================================================
__device__ __forceinline__ void gemm_tile_f32(
    const float* __restrict__ Ag, const float* __restrict__ Bg,
    float (*As)[65], float (*Bs)[132], float acc[4][8], int tid)
{
    const int a_r = tid >> 2, a_c = (tid & 3) << 2;
    const int b_r = tid >> 1, b_c = (tid & 1) << 3;
    const int rbase = (tid >> 4) * 4;
    const int cbase = (tid & 15) * 8;

    #pragma unroll
    for (int i = 0; i < 4; i++)
        #pragma unroll
        for (int j = 0; j < 8; j++) acc[i][j] = 0.f;

    float4 aR  = *(const float4*)(Ag + (size_t)a_r * DIM + a_c);
    float4 bR0 = *(const float4*)(Bg + (size_t)b_r * DIM + b_c);
    float4 bR1 = *(const float4*)(Bg + (size_t)b_r * DIM + b_c + 4);

    for (int kd = 0; kd < DIM; kd += 16) {
        As[a_c + 0][a_r] = aR.x; As[a_c + 1][a_r] = aR.y;
        As[a_c + 2][a_r] = aR.z; As[a_c + 3][a_r] = aR.w;
        Bs[b_c + 0][b_r] = bR0.x; Bs[b_c + 1][b_r] = bR0.y;
        Bs[b_c + 2][b_r] = bR0.z; Bs[b_c + 3][b_r] = bR0.w;
        Bs[b_c + 4][b_r] = bR1.x; Bs[b_c + 5][b_r] = bR1.y;
        Bs[b_c + 6][b_r] = bR1.z; Bs[b_c + 7][b_r] = bR1.w;
        __syncthreads();

        int kn = kd + 16;
        if (kn < DIM) {
            aR  = *(const float4*)(Ag + (size_t)a_r * DIM + kn + a_c);
            bR0 = *(const float4*)(Bg + (size_t)b_r * DIM + kn + b_c);
            bR1 = *(const float4*)(Bg + (size_t)b_r * DIM + kn + b_c + 4);
        }
        #pragma unroll
        for (int kk = 0; kk < 16; kk++) {
            float aa[4];
            aa[0] = As[kk][rbase + 0]; aa[1] = As[kk][rbase + 1];
            aa[2] = As[kk][rbase + 2]; aa[3] = As[kk][rbase + 3];
            float4 bv0 = *(const float4*)&Bs[kk][cbase];
            float4 bv1 = *(const float4*)&Bs[kk][cbase + 4];
            float bb[8] = {bv0.x, bv0.y, bv0.z, bv0.w, bv1.x, bv1.y, bv1.z, bv1.w};
            #pragma unroll
            for (int i = 0; i < 4; i++)
                #pragma unroll
                for (int j = 0; j < 8; j++)
                    acc[i][j] = fmaf(aa[i], bb[j], acc[i][j]);
        }
        __syncthreads();
    }
}

__global__ void __launch_bounds__(256)
h_kernel(const float* __restrict__ X, const float* __restrict__ W1,
         const float* __restrict__ b1)
{
    __shared__ __align__(16) float As[16][65];
    __shared__ __align__(16) float Bs[16][132];

    const int tid  = threadIdx.x;
    const int row0 = blockIdx.x * 64;
    const int col0 = blockIdx.y * 128;
    const int rbase = (tid >> 4) * 4;
    const int cbase = (tid & 15) * 8;

    float acc[4][8];
    gemm_tile_f32(X + (size_t)row0 * DIM, W1 + (size_t)col0 * DIM, As, Bs, acc, tid);

    float bb[8];
    #pragma unroll
    for (int j = 0; j < 8; j++) bb[j] = b1[col0 + cbase + j];

    #pragma unroll
    for (int i = 0; i < 4; i++) {
        float v[8];
        #pragma unroll
        for (int j = 0; j < 8; j++) {
            float h = acc[i][j] + bb[j];
            v[j] = (h >= 0.f) ? h : NEG_SLOPE * h;
        }
        float* dst = g_H + (size_t)(row0 + rbase + i) * DIM + col0 + cbase;
        *(float4*)(dst)     = make_float4(v[0], v[1], v[2], v[3]);
        *(float4*)(dst + 4) = make_float4(v[4], v[5], v[6], v[7]);
    }
}

// ============================================================
// TF32 tensor-core GEMM machinery (m16n8k8)
// ============================================================
#define TM_  128
#define TN_  128
#define TK_  32
#define SROW 36                       // padded smem row stride (floats)
#define STAGE_F (TM_*SROW + TN_*SROW) // 9216 floats per stage
#define NSTAGE 3
#define SMEM_BYTES (NSTAGE * STAGE_F * 4)
#define NKCH (DIM / TK_)              // 16 k-chunks

__device__ __forceinline__ void mma_tf32(float* d, const unsigned* a, const unsigned* b) {
    asm volatile(
        "mma.sync.aligned.m16n8k8.row.col.f32.tf32.tf32.f32 "
        "{%0,%1,%2,%3},{%4,%5,%6,%7},{%8,%9},{%0,%1,%2,%3};"
        : "+f"(d[0]), "+f"(d[1]), "+f"(d[2]), "+f"(d[3])
        : "r"(a[0]), "r"(a[1]), "r"(a[2]), "r"(a[3]), "r"(b[0]), "r"(b[1]));
}

__device__ __forceinline__ void cp16(float* dst, const float* src) {
    unsigned d = (unsigned)__cvta_generic_to_shared(dst);
    asm volatile("cp.async.cg.shared.global [%0], [%1], 16;" :: "r"(d), "l"(src));
}

__device__ __forceinline__ void load_tile(float* sA, float* sB,
                                          const float* Ag, const float* Bg,
                                          int kb, int tid)
{
    #pragma unroll
    for (int it = 0; it < 4; it++) {
        int f  = tid + it * 256;          // 0..1023
        int r  = f >> 3;
        int c4 = (f & 7) << 2;
        cp16(sA + r * SROW + c4, Ag + (size_t)r * DIM + kb + c4);
        cp16(sB + r * SROW + c4, Bg + (size_t)r * DIM + kb + c4);
    }
    asm volatile("cp.async.commit_group;" ::: "memory");
}

__device__ __forceinline__ void compute_stage(const float* sA, const float* sB,
                                              float acc[4][4][4],
                                              int wm, int wn, int lr, int lq)
{
    #pragma unroll
    for (int k8 = 0; k8 < 4; k8++) {
        const int kk = k8 * 8;
        unsigned a[4][4], b[4][2];
        #pragma unroll
        for (int mi = 0; mi < 4; mi++) {
            const float* ap = sA + (wm * 64 + mi * 16 + lr) * SROW + kk + lq;
            a[mi][0] = __float_as_uint(ap[0]);
            a[mi][1] = __float_as_uint(ap[8 * SROW]);
            a[mi][2] = __float_as_uint(ap[4]);
            a[mi][3] = __float_as_uint(ap[8 * SROW + 4]);
        }
        #pragma unroll
        for (int ni = 0; ni < 4; ni++) {
            const float* bp = sB + (wn * 32 + ni * 8 + lr) * SROW + kk + lq;
            b[ni][0] = __float_as_uint(bp[0]);
            b[ni][1] = __float_as_uint(bp[4]);
        }
        #pragma unroll
        for (int mi = 0; mi < 4; mi++)
            #pragma unroll
            for (int ni = 0; ni < 4; ni++)
                mma_tf32(acc[mi][ni], a[mi], b[ni]);
    }
}

// run full K=512 over one 128x128 tile with 3-stage cp.async pipeline
__device__ __forceinline__ void gemm_tile_tc(const float* Ag, const float* Bg,
                                             float* sm, float acc[4][4][4],
                                             int tid, int wm, int wn, int lr, int lq)
{
    #pragma unroll
    for (int mi = 0; mi < 4; mi++)
        #pragma unroll
        for (int ni = 0; ni < 4; ni++)
            #pragma unroll
            for (int j = 0; j < 4; j++) acc[mi][ni][j] = 0.f;

    __syncthreads();  // buffers free (prev tile fully consumed)
    load_tile(sm + 0 * STAGE_F, sm + 0 * STAGE_F + TM_ * SROW, Ag, Bg, 0, tid);
    load_tile(sm + 1 * STAGE_F, sm + 1 * STAGE_F + TM_ * SROW, Ag, Bg, TK_, tid);

    for (int kt = 0; kt < NKCH; kt++) {
        if (kt < NKCH - 1) asm volatile("cp.async.wait_group 1;" ::: "memory");
        else               asm volatile("cp.async.wait_group 0;" ::: "memory");
        __syncthreads();
        const float* buf = sm + (kt % NSTAGE) * STAGE_F;
        compute_stage(buf, buf + TM_ * SROW, acc, wm, wn, lr, lq);
        if (kt + 2 < NKCH) {
            float* nb = sm + ((kt + 2) % NSTAGE) * STAGE_F;
            load_tile(nb, nb + TM_ * SROW, Ag, Bg, (kt + 2) * TK_, tid);
        }
    }
}

// top-2 insertion (min), with index tiebreak + dedupe
__device__ __forceinline__ void ins_min(float v, int i, float& v1, int& i1, float& v2, int& i2) {
    if (v < v1 || (v == v1 && i < i1)) {
        if (i != i1) { v2 = v1; i2 = i1; }
        v1 = v; i1 = i;
    } else if (i != i1 && (v < v2 || (v == v2 && i < i2))) {
        v2 = v; i2 = i;
    }
}
__device__ __forceinline__ void ins_max(float v, int i, float& v1, int& i1, float& v2, int& i2) {
    if (v > v1 || (v == v1 && i < i1)) {
        if (i != i1) { v2 = v1; i2 = i1; }
        v1 = v; i1 = i;
    } else if (i != i1 && (v > v2 || (v == v2 && i < i2))) {
        v2 = v; i2 = i;
    }
}

// ============================================================
// mel: TF32 GEMM + fused top-2 argmin of (||e||^2 - 2 x.e)
// ============================================================
__global__ void __launch_bounds__(256, 1)
mel_mma_kernel(const float* __restrict__ X, const float* __restrict__ E)
{
    extern __shared__ float sm[];
    const int tid = threadIdx.x, w = tid >> 5, lane = tid & 31;
    const int wm = w >> 2, wn = w & 3, lr = lane >> 2, lq = lane & 3;
    const int row0 = blockIdx.x * TM_;
    const float* Ag = X + (size_t)row0 * DIM;

    float v1[8], v2[8]; int i1[8], i2[8];
    #pragma unroll
    for (int s = 0; s < 8; s++) { v1[s] = INFINITY; v2[s] = INFINITY; i1[s] = 0x7fffffff; i2[s] = 0x7fffffff; }

    float acc[4][4][4];
    for (int nt = 0; nt < KNUM / TN_; nt++) {
        const float* Bg = E + (size_t)nt * TN_ * DIM;
        gemm_tile_tc(Ag, Bg, sm, acc, tid, wm, wn, lr, lq);

        float eq[4][2];
        #pragma unroll
        for (int ni = 0; ni < 4; ni++)
            #pragma unroll
            for (int cc = 0; cc < 2; cc++)
                eq[ni][cc] = __ldg(&g_esq[nt * TN_ + wn * 32 + ni * 8 + lq * 2 + cc]);

        #pragma unroll
        for (int mi = 0; mi < 4; mi++)
            #pragma unroll
            for (int h = 0; h < 2; h++) {
                const int st = mi * 2 + h;
                #pragma unroll
                for (int ni = 0; ni < 4; ni++)
                    #pragma unroll
                    for (int cc = 0; cc < 2; cc++) {
                        float d = fmaf(-2.f, acc[mi][ni][h * 2 + cc], eq[ni][cc]);
                        int col = nt * TN_ + wn * 32 + ni * 8 + lq * 2 + cc;
                        if (d < v1[st]) { v2[st] = v1[st]; i2[st] = i1[st]; v1[st] = d; i1[st] = col; }
                        else if (d < v2[st]) { v2[st] = d; i2[st] = col; }
                    }
            }
    }

    __syncthreads();
    float* v1s = sm; float* v2s = sm + 2048;
    int* i1s = (int*)(sm + 4096); int* i2s = (int*)(sm + 6144);
    const int slot = wn * 4 + lq;
    #pragma unroll
    for (int mi = 0; mi < 4; mi++)
        #pragma unroll
        for (int h = 0; h < 2; h++) {
            int r = wm * 64 + mi * 16 + lr + h * 8;
            int st = mi * 2 + h;
            v1s[r * 16 + slot] = v1[st]; v2s[r * 16 + slot] = v2[st];
            i1s[r * 16 + slot] = i1[st]; i2s[r * 16 + slot] = i2[st];
        }
    __syncthreads();
    if (tid < TM_) {
        float bv1 = INFINITY, bv2 = INFINITY; int bi1 = 0x7fffffff, bi2 = 0x7fffffff;
        #pragma unroll
        for (int s = 0; s < 16; s++) {
            ins_min(v1s[tid * 16 + s], i1s[tid * 16 + s], bv1, bi1, bv2, bi2);
            ins_min(v2s[tid * 16 + s], i2s[tid * 16 + s], bv1, bi1, bv2, bi2);
        }
        g_meli1[row0 + tid] = bi1;
        g_meli2[row0 + tid] = bi2;
    }
}

// ============================================================
// logits: TF32 GEMM + fused top-2 argmax + online logsumexp
// ============================================================
__global__ void __launch_bounds__(256, 1)
logits_mma_kernel(const float* __restrict__ W2, const float* __restrict__ b2)
{
    extern __shared__ float sm[];
    const int tid = threadIdx.x, w = tid >> 5, lane = tid & 31;
    const int wm = w >> 2, wn = w & 3, lr = lane >> 2, lq = lane & 3;
    const int row0 = blockIdx.x * TM_;
    const float* Ag = g_H + (size_t)row0 * DIM;

    float v1[8], v2[8], m[8], s[8]; int i1[8], i2[8];
    #pragma unroll
    for (int st = 0; st < 8; st++) {
        v1[st] = -INFINITY; v2[st] = -INFINITY; i1[st] = 0x7fffffff; i2[st] = 0x7fffffff;
        m[st] = -INFINITY; s[st] = 0.f;
    }

    float acc[4][4][4];
    for (int nt = 0; nt < KNUM / TN_; nt++) {
        const float* Bg = W2 + (size_t)nt * TN_ * DIM;
        gemm_tile_tc(Ag, Bg, sm, acc, tid, wm, wn, lr, lq);

        float bb[4][2];
        #pragma unroll
        for (int ni = 0; ni < 4; ni++)
            #pragma unroll
            for (int cc = 0; cc < 2; cc++)
                bb[ni][cc] = __ldg(&b2[nt * TN_ + wn * 32 + ni * 8 + lq * 2 + cc]);

        #pragma unroll
        for (int mi = 0; mi < 4; mi++)
            #pragma unroll
            for (int h = 0; h < 2; h++) {
                const int st = mi * 2 + h;
                float x8[8];
                float mloc = -INFINITY;
                #pragma unroll
                for (int ni = 0; ni < 4; ni++)
                    #pragma unroll
                    for (int cc = 0; cc < 2; cc++) {
                        float x = acc[mi][ni][h * 2 + cc] + bb[ni][cc];
                        x8[ni * 2 + cc] = x;
                        mloc = fmaxf(mloc, x);
                        int col = nt * TN_ + wn * 32 + ni * 8 + lq * 2 + cc;
                        if (x > v1[st]) { v2[st] = v1[st]; i2[st] = i1[st]; v1[st] = x; i1[st] = col; }
                        else if (x > v2[st]) { v2[st] = x; i2[st] = col; }
                    }
                float mn = fmaxf(m[st], mloc);
                float ss = 0.f;
                #pragma unroll
                for (int e = 0; e < 8; e++) ss += __expf(x8[e] - mn);
                s[st] = fmaf(s[st], __expf(m[st] - mn), ss);
                m[st] = mn;
            }
    }

    __syncthreads();
    float* v1s = sm;                 float* v2s = sm + 2048;
    int*   i1s = (int*)(sm + 4096);  int*   i2s = (int*)(sm + 6144);
    float* ms  = sm + 8192;          float* ss  = sm + 10240;
    const int slot = wn * 4 + lq;
    #pragma unroll
    for (int mi = 0; mi < 4; mi++)
        #pragma unroll
        for (int h = 0; h < 2; h++) {
            int r = wm * 64 + mi * 16 + lr + h * 8;
            int st = mi * 2 + h;
            v1s[r * 16 + slot] = v1[st]; v2s[r * 16 + slot] = v2[st];
            i1s[r * 16 + slot] = i1[st]; i2s[r * 16 + slot] = i2[st];
            ms[r * 16 + slot] = m[st];   ss[r * 16 + slot] = s[st];
        }
    __syncthreads();
    if (tid < TM_) {
        float bv1 = -INFINITY, bv2 = -INFINITY; int bi1 = 0x7fffffff, bi2 = 0x7fffffff;
        float M = -INFINITY;
        #pragma unroll
        for (int k = 0; k < 16; k++) {
            ins_max(v1s[tid * 16 + k], i1s[tid * 16 + k], bv1, bi1, bv2, bi2);
            ins_max(v2s[tid * 16 + k], i2s[tid * 16 + k], bv1, bi1, bv2, bi2);
            M = fmaxf(M, ms[tid * 16 + k]);
        }
        float S = 0.f;
        #pragma unroll
        for (int k = 0; k < 16; k++) S += ss[tid * 16 + k] * __expf(ms[tid * 16 + k] - M);
        g_logi1[row0 + tid] = bi1;
        g_logi2[row0 + tid] = bi2;
        g_lse[row0 + tid]   = M + logf(S);
    }
}

// ============================================================
// fp32 refine: exact re-evaluation of top-2 candidates per row
// ============================================================
__device__ __forceinline__ float dot512(const float* __restrict__ a,
                                        const float* __restrict__ b, int lane)
{
    float s = 0.f;
    #pragma unroll
    for (int t = 0; t < 4; t++) {
        float4 x = *(const float4*)(a + (lane + 32 * t) * 4);
        float4 y = *(const float4*)(b + (lane + 32 * t) * 4);
        s = fmaf(x.x, y.x, s); s = fmaf(x.y, y.y, s);
        s = fmaf(x.z, y.z, s); s = fmaf(x.w, y.w, s);
    }
    #pragma unroll
    for (int o = 16; o; o >>= 1) s += __shfl_xor_sync(0xffffffffu, s, o);
    return s;
}

__global__ void __launch_bounds__(256)
refine_kernel(const float* __restrict__ Xmel, const float* __restrict__ E,
              const float* __restrict__ W2,  const float* __restrict__ b2)
{
    const int warp = threadIdx.x >> 5, lane = threadIdx.x & 31;
    const int row = blockIdx.x * 8 + warp;
    if (row >= BSZ) return;

    const float* xr = Xmel + (size_t)row * DIM;
    const float* hr = g_H  + (size_t)row * DIM;

    // mel argmin (exact fp32)
    int mi1 = g_meli1[row], mi2 = g_meli2[row];
    float d1 = g_esq[mi1] - 2.f * dot512(xr, E + (size_t)mi1 * DIM, lane);
    float d2 = g_esq[mi2] - 2.f * dot512(xr, E + (size_t)mi2 * DIM, lane);
    int mel_idx = (d1 < d2 || (d1 == d2 && mi1 < mi2)) ? mi1 : mi2;

    // eeg argmax (exact fp32)
    int j1 = g_logi1[row], j2 = g_logi2[row];
    float l1 = dot512(hr, W2 + (size_t)j1 * DIM, lane) + b2[j1];
    float l2 = dot512(hr, W2 + (size_t)j2 * DIM, lane) + b2[j2];
    int eeg_idx = (l1 > l2 || (l1 == l2 && j1 < j2)) ? j1 : j2;

    // target logit (exact fp32)
    float t = dot512(hr, W2 + (size_t)mel_idx * DIM, lane) + b2[mel_idx];

    if (lane == 0) {
        g_loss[row]  = g_lse[row] - t;
        g_match[row] = (eeg_idx == mel_idx) ? 1.f : 0.f;
    }
}

// ============================================================
// final mean reduction
// ============================================================
__global__ void reduce_kernel(float* __restrict__ out) {
    __shared__ float sl[1024];
    __shared__ float sa[1024];
    int tid = threadIdx.x;
    float a = 0.f, b = 0.f;
    for (int i = tid; i < BSZ; i += 1024) { a += g_loss[i]; b += g_match[i]; }
    sl[tid] = a; sa[tid] = b;
    __syncthreads();
    for (int o = 512; o; o >>= 1) {
        if (tid < o) { sl[tid] += sl[tid + o]; sa[tid] += sa[tid + o]; }
        __syncthreads();
    }
    if (tid == 0) {
        out[0] = sl[0] / (float)BSZ;
        out[1] = sa[0] / (float)BSZ;
    }
}

// ============================================================
extern "C" void kernel_launch(void* const* d_in, const int* in_sizes, int n_in,
                              void* d_out, int out_size)
{
    (void)in_sizes; (void)n_in; (void)out_size;
    const float* eeg = (const float*)d_in[0];
    const float* mel = (const float*)d_in[1];
    const float* emb = (const float*)d_in[2];
    const float* W1  = (const float*)d_in[3];
    const float* b1  = (const float*)d_in[4];
    const float* W2  = (const float*)d_in[5];
    const float* b2  = (const float*)d_in[6];
    float* out = (float*)d_out;

    cudaFuncSetAttribute(mel_mma_kernel,    cudaFuncAttributeMaxDynamicSharedMemorySize, SMEM_BYTES);
    cudaFuncSetAttribute(logits_mma_kernel, cudaFuncAttributeMaxDynamicSharedMemorySize, SMEM_BYTES);

    esq_kernel<<<KNUM / 8, 256>>>(emb);
    h_kernel<<<dim3(BSZ / 64, DIM / 128), 256>>>(eeg, W1, b1);
    mel_mma_kernel<<<BSZ / TM_, 256, SMEM_BYTES>>>(mel, emb);
    logits_mma_kernel<<<BSZ / TM_, 256, SMEM_BYTES>>>(W2, b2);
    refine_kernel<<<BSZ / 8, 256>>>(mel, emb, W2, b2);
    reduce_kernel<<<1, 1024>>>(out);
}

// round 5
// speedup vs baseline: 1.0475x; 1.0475x over previous
#include <cuda_runtime.h>
#include <math.h>
#include <stdint.h>

#define BSZ   16384
#define DIM   512
#define KNUM  8192
#define NEG_SLOPE 0.01f

// ---- scratch (static device globals) ----
__device__ float g_esq[KNUM];
__device__ float g_H[(size_t)BSZ * DIM];   // fp32 hidden, 32 MB
__device__ int   g_meli1[BSZ], g_meli2[BSZ];
__device__ int   g_logi1[BSZ], g_logi2[BSZ];
__device__ float g_lse[BSZ];
__device__ float g_loss[BSZ], g_match[BSZ];

// ============================================================
// TF32 mma.sync machinery (legacy path; tcgen05 unavailable at compute_103)
// ============================================================
#define SROW    36                       // padded smem row stride (floats)
#define STAGE_F ((128 + 128) * SROW)     // 9216 floats per stage (A128 + B128)
#define NSTAGE  3
#define SMEM_BYTES (NSTAGE * STAGE_F * 4)

__device__ __forceinline__ void mma_tf32(float* d, const unsigned* a, const unsigned* b) {
    asm volatile(
        "mma.sync.aligned.m16n8k8.row.col.f32.tf32.tf32.f32 "
        "{%0,%1,%2,%3},{%4,%5,%6,%7},{%8,%9},{%0,%1,%2,%3};"
        : "+f"(d[0]), "+f"(d[1]), "+f"(d[2]), "+f"(d[3])
        : "r"(a[0]), "r"(a[1]), "r"(a[2]), "r"(a[3]), "r"(b[0]), "r"(b[1]));
}

__device__ __forceinline__ void cp16(float* dst, const float* src) {
    unsigned d;
    asm("{ .reg .u64 t; cvta.to.shared.u64 t, %1; cvt.u32.u64 %0, t; }" : "=r"(d) : "l"(dst));
    asm volatile("cp.async.cg.shared.global [%0], [%1], 16;" :: "r"(d), "l"(src));
}
#define CP_COMMIT() asm volatile("cp.async.commit_group;" ::: "memory")

// 512-thread chunk loader: A[128][32] + B[128][32] fp32 -> one stage
__device__ __forceinline__ void ld_chunk512(float* sA, float* sB,
                                            const float* Ag, const float* Bg,
                                            int kb, int tid)
{
    #pragma unroll
    for (int i = 0; i < 2; i++) {
        int f  = tid + (i << 9);         // 0..1023
        int r  = f >> 3;
        int c4 = (f & 7) << 2;
        cp16(sA + r * SROW + c4, Ag + (size_t)r * DIM + kb + c4);
        cp16(sB + r * SROW + c4, Bg + (size_t)r * DIM + kb + c4);
    }
    CP_COMMIT();
}

// 16-warp compute: warp tile 32x32, acc[2][4][4]
__device__ __forceinline__ void compute_stage16(const float* sA, const float* sB,
                                                float acc[2][4][4],
                                                int wm, int wn, int lr, int lq)
{
    #pragma unroll
    for (int k8 = 0; k8 < 4; k8++) {
        const int kk = k8 * 8;
        unsigned a[2][4], b[4][2];
        #pragma unroll
        for (int mi = 0; mi < 2; mi++) {
            const float* ap = sA + (wm * 32 + mi * 16 + lr) * SROW + kk + lq;
            a[mi][0] = __float_as_uint(ap[0]);
            a[mi][1] = __float_as_uint(ap[8 * SROW]);
            a[mi][2] = __float_as_uint(ap[4]);
            a[mi][3] = __float_as_uint(ap[8 * SROW + 4]);
        }
        #pragma unroll
        for (int ni = 0; ni < 4; ni++) {
            const float* bp = sB + (wn * 32 + ni * 8 + lr) * SROW + kk + lq;
            b[ni][0] = __float_as_uint(bp[0]);
            b[ni][1] = __float_as_uint(bp[4]);
        }
        #pragma unroll
        for (int mi = 0; mi < 2; mi++)
            #pragma unroll
            for (int ni = 0; ni < 4; ni++)
                mma_tf32(acc[mi][ni], a[mi], b[ni]);
    }
}

// full K=512 pass over one 128x128 tile, 3-stage pipeline (512 threads)
__device__ __forceinline__ void gemm_k512(const float* Ag, const float* Bg,
                                          float* sm, float acc[2][4][4],
                                          int tid, int wm, int wn, int lr, int lq)
{
    #pragma unroll
    for (int mi = 0; mi < 2; mi++)
        #pragma unroll
        for (int ni = 0; ni < 4; ni++)
            #pragma unroll
            for (int j = 0; j < 4; j++) acc[mi][ni][j] = 0.f;

    __syncthreads();
    ld_chunk512(sm + 0 * STAGE_F, sm + 0 * STAGE_F + 128 * SROW, Ag, Bg, 0,  tid);
    ld_chunk512(sm + 1 * STAGE_F, sm + 1 * STAGE_F + 128 * SROW, Ag, Bg, 32, tid);

    for (int kt = 0; kt < 16; kt++) {
        if (kt < 15) asm volatile("cp.async.wait_group 1;" ::: "memory");
        else         asm volatile("cp.async.wait_group 0;" ::: "memory");
        __syncthreads();
        const float* buf = sm + (kt % NSTAGE) * STAGE_F;
        compute_stage16(buf, buf + 128 * SROW, acc, wm, wn, lr, lq);
        if (kt + 2 < 16) {
            float* nb = sm + ((kt + 2) % NSTAGE) * STAGE_F;
            ld_chunk512(nb, nb + 128 * SROW, Ag, Bg, (kt + 2) * 32, tid);
        }
    }
}

// top-2 insertion with index tiebreak + dedupe
__device__ __forceinline__ void ins_min(float v, int i, float& v1, int& i1, float& v2, int& i2) {
    if (v < v1 || (v == v1 && i < i1)) {
        if (i != i1) { v2 = v1; i2 = i1; }
        v1 = v; i1 = i;
    } else if (i != i1 && (v < v2 || (v == v2 && i < i2))) { v2 = v; i2 = i; }
}
__device__ __forceinline__ void ins_max(float v, int i, float& v1, int& i1, float& v2, int& i2) {
    if (v > v1 || (v == v1 && i < i1)) {
        if (i != i1) { v2 = v1; i2 = i1; }
        v1 = v; i1 = i;
    } else if (i != i1 && (v > v2 || (v == v2 && i < i2))) { v2 = v; i2 = i; }
}

// ============================================================
// big fused kernel: 128 rows x all 8192 cols; 512 threads, 16 warps.
// LOGITS: x = D+b2 -> top2 argmax + online LSE. !LOGITS: d = esq-2D -> top2 argmin.
// ============================================================
template<bool LOGITS>
__global__ void __launch_bounds__(512, 1)
big_mma_kernel(const float* __restrict__ Ain, const float* __restrict__ B,
               const float* __restrict__ aux)
{
    extern __shared__ float sm[];
    const int tid = threadIdx.x, w = tid >> 5, lane = tid & 31;
    const int wm = w >> 2, wn = w & 3, lr = lane >> 2, lq = lane & 3;
    const int row0 = blockIdx.x * 128;
    const float* A = LOGITS ? (const float*)g_H : Ain;
    const float* Ag = A + (size_t)row0 * DIM;

    float v1[4], v2[4], m[4], s[4]; int i1[4], i2[4];
    #pragma unroll
    for (int st = 0; st < 4; st++) {
        v1[st] = LOGITS ? -INFINITY : INFINITY; v2[st] = v1[st];
        i1[st] = 0x7fffffff; i2[st] = 0x7fffffff;
        m[st] = -INFINITY; s[st] = 0.f;
    }

    float acc[2][4][4];
    for (int nt = 0; nt < KNUM / 128; nt++) {
        gemm_k512(Ag, B + (size_t)nt * 128 * DIM, sm, acc, tid, wm, wn, lr, lq);

        float ax[4][2];
        #pragma unroll
        for (int ni = 0; ni < 4; ni++)
            #pragma unroll
            for (int cc = 0; cc < 2; cc++) {
                int col = nt * 128 + wn * 32 + ni * 8 + lq * 2 + cc;
                ax[ni][cc] = LOGITS ? __ldg(&aux[col]) : __ldg(&g_esq[col]);
            }

        #pragma unroll
        for (int mi = 0; mi < 2; mi++)
            #pragma unroll
            for (int h = 0; h < 2; h++) {
                const int st = mi * 2 + h;
                if (LOGITS) {
                    float x8[8];
                    float mloc = -INFINITY;
                    #pragma unroll
                    for (int ni = 0; ni < 4; ni++)
                        #pragma unroll
                        for (int cc = 0; cc < 2; cc++) {
                            float x = acc[mi][ni][h * 2 + cc] + ax[ni][cc];
                            x8[ni * 2 + cc] = x;
                            mloc = fmaxf(mloc, x);
                            int col = nt * 128 + wn * 32 + ni * 8 + lq * 2 + cc;
                            if (x > v1[st]) { v2[st] = v1[st]; i2[st] = i1[st]; v1[st] = x; i1[st] = col; }
                            else if (x > v2[st]) { v2[st] = x; i2[st] = col; }
                        }
                    float mn = fmaxf(m[st], mloc);
                    float ssum = 0.f;
                    #pragma unroll
                    for (int e = 0; e < 8; e++) ssum += __expf(x8[e] - mn);
                    s[st] = fmaf(s[st], __expf(m[st] - mn), ssum);
                    m[st] = mn;
                } else {
                    #pragma unroll
                    for (int ni = 0; ni < 4; ni++)
                        #pragma unroll
                        for (int cc = 0; cc < 2; cc++) {
                            float d = fmaf(-2.f, acc[mi][ni][h * 2 + cc], ax[ni][cc]);
                            int col = nt * 128 + wn * 32 + ni * 8 + lq * 2 + cc;
                            if (d < v1[st]) { v2[st] = v1[st]; i2[st] = i1[st]; v1[st] = d; i1[st] = col; }
                            else if (d < v2[st]) { v2[st] = d; i2[st] = col; }
                        }
                }
            }
    }

    // merge: 16 slots per row (wn x lq), rows 0..127
    __syncthreads();
    float* v1s = sm;                  float* v2s = sm + 2048;
    int*   i1s = (int*)(sm + 4096);   int*   i2s = (int*)(sm + 6144);
    float* ms  = sm + 8192;           float* ss  = sm + 10240;
    const int slot = wn * 4 + lq;
    #pragma unroll
    for (int mi = 0; mi < 2; mi++)
        #pragma unroll
        for (int h = 0; h < 2; h++) {
            int r  = wm * 32 + mi * 16 + lr + h * 8;
            int st = mi * 2 + h;
            v1s[r * 16 + slot] = v1[st]; v2s[r * 16 + slot] = v2[st];
            i1s[r * 16 + slot] = i1[st]; i2s[r * 16 + slot] = i2[st];
            if (LOGITS) { ms[r * 16 + slot] = m[st]; ss[r * 16 + slot] = s[st]; }
        }
    __syncthreads();
    if (tid < 128) {
        const int grow = row0 + tid;
        if (LOGITS) {
            float bv1 = -INFINITY, bv2 = -INFINITY; int bi1 = 0x7fffffff, bi2 = 0x7fffffff;
            float M = -INFINITY;
            #pragma unroll
            for (int k = 0; k < 16; k++) {
                ins_max(v1s[tid * 16 + k], i1s[tid * 16 + k], bv1, bi1, bv2, bi2);
                ins_max(v2s[tid * 16 + k], i2s[tid * 16 + k], bv1, bi1, bv2, bi2);
                M = fmaxf(M, ms[tid * 16 + k]);
            }
            float S = 0.f;
            #pragma unroll
            for (int k = 0; k < 16; k++) S += ss[tid * 16 + k] * __expf(ms[tid * 16 + k] - M);
            g_logi1[grow] = bi1; g_logi2[grow] = bi2;
            g_lse[grow]   = M + logf(S);
        } else {
            float bv1 = INFINITY, bv2 = INFINITY; int bi1 = 0x7fffffff, bi2 = 0x7fffffff;
            #pragma unroll
            for (int k = 0; k < 16; k++) {
                ins_min(v1s[tid * 16 + k], i1s[tid * 16 + k], bv1, bi1, bv2, bi2);
                ins_min(v2s[tid * 16 + k], i2s[tid * 16 + k], bv1, bi1, bv2, bi2);
            }
            g_meli1[grow] = bi1; g_meli2[grow] = bi2;
        }
    }
}

// ============================================================
// H = leakyrelu(X*W1^T + b1) via 3xTF32 split (fp32-equivalent precision)
// ============================================================
__device__ __forceinline__ void split_tf32(float x, unsigned& hi, unsigned& lo) {
    unsigned xb = __float_as_uint(x);
    unsigned hb = xb & 0xFFFFE000u;
    hi = hb;
    lo = __float_as_uint(x - __uint_as_float(hb));
}

__device__ __forceinline__ void compute_stage16_3x(const float* sA, const float* sB,
                                                   float acc[2][4][4],
                                                   int wm, int wn, int lr, int lq)
{
    #pragma unroll
    for (int k8 = 0; k8 < 4; k8++) {
        const int kk = k8 * 8;
        unsigned ah[2][4], al[2][4], bh[4][2], bl[4][2];
        #pragma unroll
        for (int mi = 0; mi < 2; mi++) {
            const float* ap = sA + (wm * 32 + mi * 16 + lr) * SROW + kk + lq;
            split_tf32(ap[0],            ah[mi][0], al[mi][0]);
            split_tf32(ap[8 * SROW],     ah[mi][1], al[mi][1]);
            split_tf32(ap[4],            ah[mi][2], al[mi][2]);
            split_tf32(ap[8 * SROW + 4], ah[mi][3], al[mi][3]);
        }
        #pragma unroll
        for (int ni = 0; ni < 4; ni++) {
            const float* bp = sB + (wn * 32 + ni * 8 + lr) * SROW + kk + lq;
            split_tf32(bp[0], bh[ni][0], bl[ni][0]);
            split_tf32(bp[4], bh[ni][1], bl[ni][1]);
        }
        #pragma unroll
        for (int mi = 0; mi < 2; mi++)
            #pragma unroll
            for (int ni = 0; ni < 4; ni++) {
                mma_tf32(acc[mi][ni], ah[mi], bh[ni]);
                mma_tf32(acc[mi][ni], ah[mi], bl[ni]);
                mma_tf32(acc[mi][ni], al[mi], bh[ni]);
            }
    }
}

__global__ void __launch_bounds__(512, 1)
h_mma_kernel(const float* __restrict__ X, const float* __restrict__ W1,
             const float* __restrict__ b1)
{
    extern __shared__ float sm[];
    const int tid = threadIdx.x, w = tid >> 5, lane = tid & 31;
    const int wm = w >> 2, wn = w & 3, lr = lane >> 2, lq = lane & 3;
    const int row0 = blockIdx.x * 128;
    const int col0 = blockIdx.y * 128;
    const float* Ag = X  + (size_t)row0 * DIM;
    const float* Bg = W1 + (size_t)col0 * DIM;

    float acc[2][4][4];
    #pragma unroll
    for (int mi = 0; mi < 2; mi++)
        #pragma unroll
        for (int ni = 0; ni < 4; ni++)
            #pragma unroll
            for (int j = 0; j < 4; j++) acc[mi][ni][j] = 0.f;

    __syncthreads();
    ld_chunk512(sm + 0 * STAGE_F, sm + 0 * STAGE_F + 128 * SROW, Ag, Bg, 0,  tid);
    ld_chunk512(sm + 1 * STAGE_F, sm + 1 * STAGE_F + 128 * SROW, Ag, Bg, 32, tid);

    for (int kt = 0; kt < 16; kt++) {
        if (kt < 15) asm volatile("cp.async.wait_group 1;" ::: "memory");
        else         asm volatile("cp.async.wait_group 0;" ::: "memory");
        __syncthreads();
        const float* buf = sm + (kt % NSTAGE) * STAGE_F;
        compute_stage16_3x(buf, buf + 128 * SROW, acc, wm, wn, lr, lq);
        if (kt + 2 < 16) {
            float* nb = sm + ((kt + 2) % NSTAGE) * STAGE_F;
            ld_chunk512(nb, nb + 128 * SROW, Ag, Bg, (kt + 2) * 32, tid);
        }
    }

    // epilogue: bias + leakyrelu + store float2
    #pragma unroll
    for (int mi = 0; mi < 2; mi++)
        #pragma unroll
        for (int h = 0; h < 2; h++) {
            int r = row0 + wm * 32 + mi * 16 + lr + h * 8;
            #pragma unroll
            for (int ni = 0; ni < 4; ni++) {
                int c = col0 + wn * 32 + ni * 8 + lq * 2;
                float x0 = acc[mi][ni][h * 2 + 0] + __ldg(&b1[c + 0]);
                float x1 = acc[mi][ni][h * 2 + 1] + __ldg(&b1[c + 1]);
                x0 = (x0 >= 0.f) ? x0 : NEG_SLOPE * x0;
                x1 = (x1 >= 0.f) ? x1 : NEG_SLOPE * x1;
                *(float2*)(g_H + (size_t)r * DIM + c) = make_float2(x0, x1);
            }
        }
}

// ============================================================
// ||e_k||^2
// ============================================================
__global__ void esq_kernel(const float* __restrict__ E) {
    int row  = blockIdx.x * (blockDim.x >> 5) + (threadIdx.x >> 5);
    int lane = threadIdx.x & 31;
    const float* e = E + (size_t)row * DIM;
    float s = 0.f;
    for (int c = lane; c < DIM; c += 32) { float v = e[c]; s = fmaf(v, v, s); }
    #pragma unroll
    for (int o = 16; o; o >>= 1) s += __shfl_xor_sync(0xffffffffu, s, o);
    if (lane == 0) g_esq[row] = s;
}

// ============================================================
// fp32 refine: exact re-evaluation of top-2 candidates per row
// ============================================================
__device__ __forceinline__ float dot512(const float* __restrict__ a,
                                        const float* __restrict__ b, int lane)
{
    float s = 0.f;
    #pragma unroll
    for (int t = 0; t < 4; t++) {
        float4 x = *(const float4*)(a + (lane + 32 * t) * 4);
        float4 y = *(const float4*)(b + (lane + 32 * t) * 4);
        s = fmaf(x.x, y.x, s); s = fmaf(x.y, y.y, s);
        s = fmaf(x.z, y.z, s); s = fmaf(x.w, y.w, s);
    }
    #pragma unroll
    for (int o = 16; o; o >>= 1) s += __shfl_xor_sync(0xffffffffu, s, o);
    return s;
}

__global__ void __launch_bounds__(256)
refine_kernel(const float* __restrict__ Xmel, const float* __restrict__ E,
              const float* __restrict__ W2,  const float* __restrict__ b2)
{
    const int warp = threadIdx.x >> 5, lane = threadIdx.x & 31;
    const int row = blockIdx.x * 8 + warp;
    if (row >= BSZ) return;

    const float* xr = Xmel + (size_t)row * DIM;
    const float* hr = g_H  + (size_t)row * DIM;

    int mi1 = g_meli1[row], mi2 = g_meli2[row];
    float d1 = g_esq[mi1] - 2.f * dot512(xr, E + (size_t)mi1 * DIM, lane);
    float d2 = g_esq[mi2] - 2.f * dot512(xr, E + (size_t)mi2 * DIM, lane);
    int mel_idx = (d1 < d2 || (d1 == d2 && mi1 < mi2)) ? mi1 : mi2;

    int j1 = g_logi1[row], j2 = g_logi2[row];
    float l1 = dot512(hr, W2 + (size_t)j1 * DIM, lane) + b2[j1];
    float l2 = dot512(hr, W2 + (size_t)j2 * DIM, lane) + b2[j2];
    int eeg_idx = (l1 > l2 || (l1 == l2 && j1 < j2)) ? j1 : j2;

    float t = dot512(hr, W2 + (size_t)mel_idx * DIM, lane) + b2[mel_idx];

    if (lane == 0) {
        g_loss[row]  = g_lse[row] - t;
        g_match[row] = (eeg_idx == mel_idx) ? 1.f : 0.f;
    }
}

// ============================================================
// final mean reduction
// ============================================================
__global__ void reduce_kernel(float* __restrict__ out) {
    __shared__ float sl[1024];
    __shared__ float sa[1024];
    int tid = threadIdx.x;
    float a = 0.f, b = 0.f;
    for (int i = tid; i < BSZ; i += 1024) { a += g_loss[i]; b += g_match[i]; }
    sl[tid] = a; sa[tid] = b;
    __syncthreads();
    for (int o = 512; o; o >>= 1) {
        if (tid < o) { sl[tid] += sl[tid + o]; sa[tid] += sa[tid + o]; }
        __syncthreads();
    }
    if (tid == 0) {
        out[0] = sl[0] / (float)BSZ;
        out[1] = sa[0] / (float)BSZ;
    }
}

// ============================================================
extern "C" void kernel_launch(void* const* d_in, const int* in_sizes, int n_in,
                              void* d_out, int out_size)
{
    (void)in_sizes; (void)n_in; (void)out_size;
    const float* eeg = (const float*)d_in[0];
    const float* mel = (const float*)d_in[1];
    const float* emb = (const float*)d_in[2];
    const float* W1  = (const float*)d_in[3];
    const float* b1  = (const float*)d_in[4];
    const float* W2  = (const float*)d_in[5];
    const float* b2  = (const float*)d_in[6];
    float* out = (float*)d_out;

    cudaFuncSetAttribute(big_mma_kernel<false>, cudaFuncAttributeMaxDynamicSharedMemorySize, SMEM_BYTES);
    cudaFuncSetAttribute(big_mma_kernel<true>,  cudaFuncAttributeMaxDynamicSharedMemorySize, SMEM_BYTES);
    cudaFuncSetAttribute(h_mma_kernel,          cudaFuncAttributeMaxDynamicSharedMemorySize, SMEM_BYTES);

    esq_kernel<<<KNUM / 8, 256>>>(emb);
    h_mma_kernel<<<dim3(BSZ / 128, DIM / 128), 512, SMEM_BYTES>>>(eeg, W1, b1);
    big_mma_kernel<false><<<BSZ / 128, 512, SMEM_BYTES>>>(mel, emb, nullptr);
    big_mma_kernel<true><<<BSZ / 128, 512, SMEM_BYTES>>>(nullptr, W2, b2);
    refine_kernel<<<BSZ / 8, 256>>>(mel, emb, W2, b2);
    reduce_kernel<<<1, 1024>>>(out);
}

// round 6
// speedup vs baseline: 1.2760x; 1.2182x over previous
#include <cuda_runtime.h>
#include <math.h>
#include <stdint.h>

#define BSZ   16384
#define DIM   512
#define KNUM  8192
#define NEG_SLOPE 0.01f

// ---- scratch (static device globals) ----
__device__ float g_esq[KNUM];
__device__ float g_H[(size_t)BSZ * DIM];   // fp32 hidden, 32 MB
__device__ int   g_meli1[BSZ], g_meli2[BSZ];
__device__ int   g_logi1[BSZ], g_logi2[BSZ];
__device__ float g_lse[BSZ];
__device__ float g_loss[BSZ], g_match[BSZ];

// ============================================================
// TF32 mma.sync machinery (legacy path; tcgen05 unavailable at compute_103)
// CTA tile 128(M) x 256(N-pass), k-chunks of 32, 8 warps, warp tile 64x64.
// ============================================================
#define MROWS   128
#define NROWS   256
#define SROW    36                        // padded smem row stride (floats)
#define STAGE_F ((MROWS + NROWS) * SROW)  // 13824 floats per stage
#define NSTAGE  3
#define SMEM_BYTES (NSTAGE * STAGE_F * 4) // 165888 B

__device__ __forceinline__ void mma_tf32(float* d, const unsigned* a, const unsigned* b) {
    asm volatile(
        "mma.sync.aligned.m16n8k8.row.col.f32.tf32.tf32.f32 "
        "{%0,%1,%2,%3},{%4,%5,%6,%7},{%8,%9},{%0,%1,%2,%3};"
        : "+f"(d[0]), "+f"(d[1]), "+f"(d[2]), "+f"(d[3])
        : "r"(a[0]), "r"(a[1]), "r"(a[2]), "r"(a[3]), "r"(b[0]), "r"(b[1]));
}

__device__ __forceinline__ void cp16(float* dst, const float* src) {
    unsigned d;
    asm("{ .reg .u64 t; cvta.to.shared.u64 t, %1; cvt.u32.u64 %0, t; }" : "=r"(d) : "l"(dst));
    asm volatile("cp.async.cg.shared.global [%0], [%1], 16;" :: "r"(d), "l"(src));
}
#define CP_COMMIT() asm volatile("cp.async.commit_group;" ::: "memory")

// 256-thread chunk loader: A[128][32] + B[256][32] fp32 -> one stage
__device__ __forceinline__ void ld_chunk(float* sA, float* sB,
                                         const float* Ag, const float* Bg,
                                         int kb, int tid)
{
    #pragma unroll
    for (int i = 0; i < 4; i++) {
        int f = tid + (i << 8);
        int r = f >> 3, c4 = (f & 7) << 2;
        cp16(sA + r * SROW + c4, Ag + (size_t)r * DIM + kb + c4);
    }
    #pragma unroll
    for (int i = 0; i < 8; i++) {
        int f = tid + (i << 8);
        int r = f >> 3, c4 = (f & 7) << 2;
        cp16(sB + r * SROW + c4, Bg + (size_t)r * DIM + kb + c4);
    }
    CP_COMMIT();
}

// 8-warp compute: warp tile 64x64, acc[4][8][4]
__device__ __forceinline__ void compute_stage(const float* sA, const float* sB,
                                              float acc[4][8][4],
                                              int wm, int wn, int lr, int lq)
{
    #pragma unroll
    for (int k8 = 0; k8 < 4; k8++) {
        const int kk = k8 * 8;
        unsigned a[4][4], b[8][2];
        #pragma unroll
        for (int mi = 0; mi < 4; mi++) {
            const float* ap = sA + (wm * 64 + mi * 16 + lr) * SROW + kk + lq;
            a[mi][0] = __float_as_uint(ap[0]);
            a[mi][1] = __float_as_uint(ap[8 * SROW]);
            a[mi][2] = __float_as_uint(ap[4]);
            a[mi][3] = __float_as_uint(ap[8 * SROW + 4]);
        }
        #pragma unroll
        for (int ni = 0; ni < 8; ni++) {
            const float* bp = sB + (wn * 64 + ni * 8 + lr) * SROW + kk + lq;
            b[ni][0] = __float_as_uint(bp[0]);
            b[ni][1] = __float_as_uint(bp[4]);
        }
        #pragma unroll
        for (int mi = 0; mi < 4; mi++)
            #pragma unroll
            for (int ni = 0; ni < 8; ni++)
                mma_tf32(acc[mi][ni], a[mi], b[ni]);
    }
}

// full K=512 pass over one 128x256 tile, 3-stage pipeline (256 threads)
__device__ __forceinline__ void gemm_k512(const float* Ag, const float* Bg,
                                          float* sm, float acc[4][8][4],
                                          int tid, int wm, int wn, int lr, int lq)
{
    #pragma unroll
    for (int mi = 0; mi < 4; mi++)
        #pragma unroll
        for (int ni = 0; ni < 8; ni++)
            #pragma unroll
            for (int j = 0; j < 4; j++) acc[mi][ni][j] = 0.f;

    __syncthreads();
    ld_chunk(sm + 0 * STAGE_F, sm + 0 * STAGE_F + MROWS * SROW, Ag, Bg, 0,  tid);
    ld_chunk(sm + 1 * STAGE_F, sm + 1 * STAGE_F + MROWS * SROW, Ag, Bg, 32, tid);

    for (int kt = 0; kt < 16; kt++) {
        if (kt < 15) asm volatile("cp.async.wait_group 1;" ::: "memory");
        else         asm volatile("cp.async.wait_group 0;" ::: "memory");
        __syncthreads();
        const float* buf = sm + (kt % NSTAGE) * STAGE_F;
        compute_stage(buf, buf + MROWS * SROW, acc, wm, wn, lr, lq);
        if (kt + 2 < 16) {
            float* nb = sm + ((kt + 2) % NSTAGE) * STAGE_F;
            ld_chunk(nb, nb + MROWS * SROW, Ag, Bg, (kt + 2) * 32, tid);
        }
    }
}

// top-2 insertion with index tiebreak + dedupe
__device__ __forceinline__ void ins_min(float v, int i, float& v1, int& i1, float& v2, int& i2) {
    if (v < v1 || (v == v1 && i < i1)) {
        if (i != i1) { v2 = v1; i2 = i1; }
        v1 = v; i1 = i;
    } else if (i != i1 && (v < v2 || (v == v2 && i < i2))) { v2 = v; i2 = i; }
}
__device__ __forceinline__ void ins_max(float v, int i, float& v1, int& i1, float& v2, int& i2) {
    if (v > v1 || (v == v1 && i < i1)) {
        if (i != i1) { v2 = v1; i2 = i1; }
        v1 = v; i1 = i;
    } else if (i != i1 && (v > v2 || (v == v2 && i < i2))) { v2 = v; i2 = i; }
}

// ============================================================
// big fused kernel: 128 rows x all 8192 cols; 256 threads, 8 warps (2x4).
// LOGITS: x = D+b2 -> top2 argmax + online LSE. !LOGITS: d = esq-2D -> top2 argmin.
// ============================================================
template<bool LOGITS>
__global__ void __launch_bounds__(256, 1)
big_mma_kernel(const float* __restrict__ Ain, const float* __restrict__ B,
               const float* __restrict__ aux)
{
    extern __shared__ float sm[];
    const int tid = threadIdx.x, w = tid >> 5, lane = tid & 31;
    const int wm = w >> 2, wn = w & 3, lr = lane >> 2, lq = lane & 3;
    const int row0 = blockIdx.x * MROWS;
    const float* A = LOGITS ? (const float*)g_H : Ain;
    const float* Ag = A + (size_t)row0 * DIM;

    float v1[8], v2[8], m[8], s[8]; int i1[8], i2[8];
    #pragma unroll
    for (int st = 0; st < 8; st++) {
        v1[st] = LOGITS ? -INFINITY : INFINITY; v2[st] = v1[st];
        i1[st] = 0x7fffffff; i2[st] = 0x7fffffff;
        m[st] = -INFINITY; s[st] = 0.f;
    }

    float acc[4][8][4];
    for (int nt = 0; nt < KNUM / NROWS; nt++) {
        gemm_k512(Ag, B + (size_t)nt * NROWS * DIM, sm, acc, tid, wm, wn, lr, lq);

        #pragma unroll
        for (int mi = 0; mi < 4; mi++)
            #pragma unroll
            for (int h = 0; h < 2; h++) {
                const int st = mi * 2 + h;
                if (LOGITS) {
                    float x16[16];
                    float mloc = -INFINITY;
                    #pragma unroll
                    for (int ni = 0; ni < 8; ni++)
                        #pragma unroll
                        for (int cc = 0; cc < 2; cc++) {
                            int col = nt * NROWS + wn * 64 + ni * 8 + lq * 2 + cc;
                            float x = acc[mi][ni][h * 2 + cc] + __ldg(&aux[col]);
                            x16[ni * 2 + cc] = x;
                            mloc = fmaxf(mloc, x);
                            if (x > v1[st]) { v2[st] = v1[st]; i2[st] = i1[st]; v1[st] = x; i1[st] = col; }
                            else if (x > v2[st]) { v2[st] = x; i2[st] = col; }
                        }
                    float mn = fmaxf(m[st], mloc);
                    float ssum = 0.f;
                    #pragma unroll
                    for (int e = 0; e < 16; e++) ssum += __expf(x16[e] - mn);
                    s[st] = fmaf(s[st], __expf(m[st] - mn), ssum);
                    m[st] = mn;
                } else {
                    #pragma unroll
                    for (int ni = 0; ni < 8; ni++)
                        #pragma unroll
                        for (int cc = 0; cc < 2; cc++) {
                            int col = nt * NROWS + wn * 64 + ni * 8 + lq * 2 + cc;
                            float d = fmaf(-2.f, acc[mi][ni][h * 2 + cc], __ldg(&g_esq[col]));
                            if (d < v1[st]) { v2[st] = v1[st]; i2[st] = i1[st]; v1[st] = d; i1[st] = col; }
                            else if (d < v2[st]) { v2[st] = d; i2[st] = col; }
                        }
                }
            }
    }

    // merge: 16 slots per row (wn x lq), rows 0..127
    __syncthreads();
    float* v1s = sm;                  float* v2s = sm + 2048;
    int*   i1s = (int*)(sm + 4096);   int*   i2s = (int*)(sm + 6144);
    float* ms  = sm + 8192;           float* ss  = sm + 10240;
    const int slot = wn * 4 + lq;
    #pragma unroll
    for (int mi = 0; mi < 4; mi++)
        #pragma unroll
        for (int h = 0; h < 2; h++) {
            int r  = wm * 64 + mi * 16 + lr + h * 8;
            int st = mi * 2 + h;
            v1s[r * 16 + slot] = v1[st]; v2s[r * 16 + slot] = v2[st];
            i1s[r * 16 + slot] = i1[st]; i2s[r * 16 + slot] = i2[st];
            if (LOGITS) { ms[r * 16 + slot] = m[st]; ss[r * 16 + slot] = s[st]; }
        }
    __syncthreads();
    if (tid < 128) {
        const int grow = row0 + tid;
        if (LOGITS) {
            float bv1 = -INFINITY, bv2 = -INFINITY; int bi1 = 0x7fffffff, bi2 = 0x7fffffff;
            float M = -INFINITY;
            #pragma unroll
            for (int k = 0; k < 16; k++) {
                ins_max(v1s[tid * 16 + k], i1s[tid * 16 + k], bv1, bi1, bv2, bi2);
                ins_max(v2s[tid * 16 + k], i2s[tid * 16 + k], bv1, bi1, bv2, bi2);
                M = fmaxf(M, ms[tid * 16 + k]);
            }
            float S = 0.f;
            #pragma unroll
            for (int k = 0; k < 16; k++) S += ss[tid * 16 + k] * __expf(ms[tid * 16 + k] - M);
            g_logi1[grow] = bi1; g_logi2[grow] = bi2;
            g_lse[grow]   = M + logf(S);
        } else {
            float bv1 = INFINITY, bv2 = INFINITY; int bi1 = 0x7fffffff, bi2 = 0x7fffffff;
            #pragma unroll
            for (int k = 0; k < 16; k++) {
                ins_min(v1s[tid * 16 + k], i1s[tid * 16 + k], bv1, bi1, bv2, bi2);
                ins_min(v2s[tid * 16 + k], i2s[tid * 16 + k], bv1, bi1, bv2, bi2);
            }
            g_meli1[grow] = bi1; g_meli2[grow] = bi2;
        }
    }
}

// ============================================================
// H = leakyrelu(X*W1^T + b1) via 3xTF32 split (fp32-equivalent precision)
// ============================================================
__device__ __forceinline__ void split_tf32(float x, unsigned& hi, unsigned& lo) {
    unsigned xb = __float_as_uint(x);
    unsigned hb = xb & 0xFFFFE000u;
    hi = hb;
    lo = __float_as_uint(x - __uint_as_float(hb));
}

__device__ __forceinline__ void compute_stage_3x(const float* sA, const float* sB,
                                                 float acc[4][8][4],
                                                 int wm, int wn, int lr, int lq)
{
    #pragma unroll
    for (int k8 = 0; k8 < 4; k8++) {
        const int kk = k8 * 8;
        unsigned ah[4][4], al[4][4], bh[8][2], bl[8][2];
        #pragma unroll
        for (int mi = 0; mi < 4; mi++) {
            const float* ap = sA + (wm * 64 + mi * 16 + lr) * SROW + kk + lq;
            split_tf32(ap[0],            ah[mi][0], al[mi][0]);
            split_tf32(ap[8 * SROW],     ah[mi][1], al[mi][1]);
            split_tf32(ap[4],            ah[mi][2], al[mi][2]);
            split_tf32(ap[8 * SROW + 4], ah[mi][3], al[mi][3]);
        }
        #pragma unroll
        for (int ni = 0; ni < 8; ni++) {
            const float* bp = sB + (wn * 64 + ni * 8 + lr) * SROW + kk + lq;
            split_tf32(bp[0], bh[ni][0], bl[ni][0]);
            split_tf32(bp[4], bh[ni][1], bl[ni][1]);
        }
        #pragma unroll
        for (int mi = 0; mi < 4; mi++)
            #pragma unroll
            for (int ni = 0; ni < 8; ni++) {
                mma_tf32(acc[mi][ni], ah[mi], bh[ni]);
                mma_tf32(acc[mi][ni], ah[mi], bl[ni]);
                mma_tf32(acc[mi][ni], al[mi], bh[ni]);
            }
    }
}

__global__ void __launch_bounds__(256, 1)
h_mma_kernel(const float* __restrict__ X, const float* __restrict__ W1,
             const float* __restrict__ b1)
{
    extern __shared__ float sm[];
    const int tid = threadIdx.x, w = tid >> 5, lane = tid & 31;
    const int wm = w >> 2, wn = w & 3, lr = lane >> 2, lq = lane & 3;
    const int row0 = blockIdx.x * MROWS;
    const int col0 = blockIdx.y * NROWS;
    const float* Ag = X  + (size_t)row0 * DIM;
    const float* Bg = W1 + (size_t)col0 * DIM;

    float acc[4][8][4];
    #pragma unroll
    for (int mi = 0; mi < 4; mi++)
        #pragma unroll
        for (int ni = 0; ni < 8; ni++)
            #pragma unroll
            for (int j = 0; j < 4; j++) acc[mi][ni][j] = 0.f;

    __syncthreads();
    ld_chunk(sm + 0 * STAGE_F, sm + 0 * STAGE_F + MROWS * SROW, Ag, Bg, 0,  tid);
    ld_chunk(sm + 1 * STAGE_F, sm + 1 * STAGE_F + MROWS * SROW, Ag, Bg, 32, tid);

    for (int kt = 0; kt < 16; kt++) {
        if (kt < 15) asm volatile("cp.async.wait_group 1;" ::: "memory");
        else         asm volatile("cp.async.wait_group 0;" ::: "memory");
        __syncthreads();
        const float* buf = sm + (kt % NSTAGE) * STAGE_F;
        compute_stage_3x(buf, buf + MROWS * SROW, acc, wm, wn, lr, lq);
        if (kt + 2 < 16) {
            float* nb = sm + ((kt + 2) % NSTAGE) * STAGE_F;
            ld_chunk(nb, nb + MROWS * SROW, Ag, Bg, (kt + 2) * 32, tid);
        }
    }

    // epilogue: bias + leakyrelu + store float2
    #pragma unroll
    for (int mi = 0; mi < 4; mi++)
        #pragma unroll
        for (int h = 0; h < 2; h++) {
            int r = row0 + wm * 64 + mi * 16 + lr + h * 8;
            #pragma unroll
            for (int ni = 0; ni < 8; ni++) {
                int c = col0 + wn * 64 + ni * 8 + lq * 2;
                float x0 = acc[mi][ni][h * 2 + 0] + __ldg(&b1[c + 0]);
                float x1 = acc[mi][ni][h * 2 + 1] + __ldg(&b1[c + 1]);
                x0 = (x0 >= 0.f) ? x0 : NEG_SLOPE * x0;
                x1 = (x1 >= 0.f) ? x1 : NEG_SLOPE * x1;
                *(float2*)(g_H + (size_t)r * DIM + c) = make_float2(x0, x1);
            }
        }
}

// ============================================================
// ||e_k||^2
// ============================================================
__global__ void esq_kernel(const float* __restrict__ E) {
    int row  = blockIdx.x * (blockDim.x >> 5) + (threadIdx.x >> 5);
    int lane = threadIdx.x & 31;
    const float* e = E + (size_t)row * DIM;
    float s = 0.f;
    for (int c = lane; c < DIM; c += 32) { float v = e[c]; s = fmaf(v, v, s); }
    #pragma unroll
    for (int o = 16; o; o >>= 1) s += __shfl_xor_sync(0xffffffffu, s, o);
    if (lane == 0) g_esq[row] = s;
}

// ============================================================
// fp32 refine: exact re-evaluation of top-2 candidates per row
// ============================================================
__device__ __forceinline__ float dot512(const float* __restrict__ a,
                                        const float* __restrict__ b, int lane)
{
    float s = 0.f;
    #pragma unroll
    for (int t = 0; t < 4; t++) {
        float4 x = *(const float4*)(a + (lane + 32 * t) * 4);
        float4 y = *(const float4*)(b + (lane + 32 * t) * 4);
        s = fmaf(x.x, y.x, s); s = fmaf(x.y, y.y, s);
        s = fmaf(x.z, y.z, s); s = fmaf(x.w, y.w, s);
    }
    #pragma unroll
    for (int o = 16; o; o >>= 1) s += __shfl_xor_sync(0xffffffffu, s, o);
    return s;
}

__global__ void __launch_bounds__(256)
refine_kernel(const float* __restrict__ Xmel, const float* __restrict__ E,
              const float* __restrict__ W2,  const float* __restrict__ b2)
{
    const int warp = threadIdx.x >> 5, lane = threadIdx.x & 31;
    const int row = blockIdx.x * 8 + warp;
    if (row >= BSZ) return;

    const float* xr = Xmel + (size_t)row * DIM;
    const float* hr = g_H  + (size_t)row * DIM;

    int mi1 = g_meli1[row], mi2 = g_meli2[row];
    float d1 = g_esq[mi1] - 2.f * dot512(xr, E + (size_t)mi1 * DIM, lane);
    float d2 = g_esq[mi2] - 2.f * dot512(xr, E + (size_t)mi2 * DIM, lane);
    int mel_idx = (d1 < d2 || (d1 == d2 && mi1 < mi2)) ? mi1 : mi2;

    int j1 = g_logi1[row], j2 = g_logi2[row];
    float l1 = dot512(hr, W2 + (size_t)j1 * DIM, lane) + b2[j1];
    float l2 = dot512(hr, W2 + (size_t)j2 * DIM, lane) + b2[j2];
    int eeg_idx = (l1 > l2 || (l1 == l2 && j1 < j2)) ? j1 : j2;

    float t = dot512(hr, W2 + (size_t)mel_idx * DIM, lane) + b2[mel_idx];

    if (lane == 0) {
        g_loss[row]  = g_lse[row] - t;
        g_match[row] = (eeg_idx == mel_idx) ? 1.f : 0.f;
    }
}

// ============================================================
// final mean reduction
// ============================================================
__global__ void reduce_kernel(float* __restrict__ out) {
    __shared__ float sl[1024];
    __shared__ float sa[1024];
    int tid = threadIdx.x;
    float a = 0.f, b = 0.f;
    for (int i = tid; i < BSZ; i += 1024) { a += g_loss[i]; b += g_match[i]; }
    sl[tid] = a; sa[tid] = b;
    __syncthreads();
    for (int o = 512; o; o >>= 1) {
        if (tid < o) { sl[tid] += sl[tid + o]; sa[tid] += sa[tid + o]; }
        __syncthreads();
    }
    if (tid == 0) {
        out[0] = sl[0] / (float)BSZ;
        out[1] = sa[0] / (float)BSZ;
    }
}

// ============================================================
extern "C" void kernel_launch(void* const* d_in, const int* in_sizes, int n_in,
                              void* d_out, int out_size)
{
    (void)in_sizes; (void)n_in; (void)out_size;
    const float* eeg = (const float*)d_in[0];
    const float* mel = (const float*)d_in[1];
    const float* emb = (const float*)d_in[2];
    const float* W1  = (const float*)d_in[3];
    const float* b1  = (const float*)d_in[4];
    const float* W2  = (const float*)d_in[5];
    const float* b2  = (const float*)d_in[6];
    float* out = (float*)d_out;

    cudaFuncSetAttribute(big_mma_kernel<false>, cudaFuncAttributeMaxDynamicSharedMemorySize, SMEM_BYTES);
    cudaFuncSetAttribute(big_mma_kernel<true>,  cudaFuncAttributeMaxDynamicSharedMemorySize, SMEM_BYTES);
    cudaFuncSetAttribute(h_mma_kernel,          cudaFuncAttributeMaxDynamicSharedMemorySize, SMEM_BYTES);

    esq_kernel<<<KNUM / 8, 256>>>(emb);
    h_mma_kernel<<<dim3(BSZ / MROWS, DIM / NROWS), 256, SMEM_BYTES>>>(eeg, W1, b1);
    big_mma_kernel<false><<<BSZ / MROWS, 256, SMEM_BYTES>>>(mel, emb, nullptr);
    big_mma_kernel<true><<<BSZ / MROWS, 256, SMEM_BYTES>>>(nullptr, W2, b2);
    refine_kernel<<<BSZ / 8, 256>>>(mel, emb, W2, b2);
    reduce_kernel<<<1, 1024>>>(out);
}

// round 7
// speedup vs baseline: 1.3331x; 1.0447x over previous
#include <cuda_runtime.h>
#include <math.h>
#include <stdint.h>

#define BSZ   16384
#define DIM   512
#define KNUM  8192
#define NEG_SLOPE 0.01f

// ---- scratch (static device globals) ----
__device__ float g_esq[KNUM];
__device__ float g_H[(size_t)BSZ * DIM];   // fp32 hidden, 32 MB
__device__ int   g_meli1[BSZ], g_meli2[BSZ];
__device__ int   g_logi1[BSZ], g_logi2[BSZ];
__device__ float g_lse[BSZ];
__device__ float g_loss[BSZ], g_match[BSZ];

// ============================================================
// TF32 mma.sync machinery (legacy path; tcgen05 unavailable at compute_103)
// CTA tile 128(M) x 256(N-pass), k-chunks of 32, 8 warps, warp tile 64x64.
// Fragments fed by ldmatrix.x4 (tf32-as-b16pair trick).
// ============================================================
#define MROWS   128
#define NROWS   256
#define SROW    36                        // padded smem row stride (floats)
#define STAGE_F ((MROWS + NROWS) * SROW)  // 13824 floats per stage
#define NSTAGE  3
#define SMEM_BYTES (NSTAGE * STAGE_F * 4) // 165888 B

__device__ __forceinline__ uint32_t smem_u32(const void* p) {
    uint32_t a;
    asm("{ .reg .u64 t; cvta.to.shared.u64 t, %1; cvt.u32.u64 %0, t; }" : "=r"(a) : "l"(p));
    return a;
}

__device__ __forceinline__ void mma_tf32(float* d, const uint32_t* a, const uint32_t* b) {
    asm volatile(
        "mma.sync.aligned.m16n8k8.row.col.f32.tf32.tf32.f32 "
        "{%0,%1,%2,%3},{%4,%5,%6,%7},{%8,%9},{%0,%1,%2,%3};"
        : "+f"(d[0]), "+f"(d[1]), "+f"(d[2]), "+f"(d[3])
        : "r"(a[0]), "r"(a[1]), "r"(a[2]), "r"(a[3]), "r"(b[0]), "r"(b[1]));
}

__device__ __forceinline__ void ldsm4(uint32_t& r0, uint32_t& r1, uint32_t& r2, uint32_t& r3,
                                      uint32_t addr) {
    asm volatile("ldmatrix.sync.aligned.m8n8.x4.shared.b16 {%0,%1,%2,%3}, [%4];"
                 : "=r"(r0), "=r"(r1), "=r"(r2), "=r"(r3) : "r"(addr));
}

__device__ __forceinline__ void cp16(float* dst, const float* src) {
    unsigned d = smem_u32(dst);
    asm volatile("cp.async.cg.shared.global [%0], [%1], 16;" :: "r"(d), "l"(src));
}
#define CP_COMMIT() asm volatile("cp.async.commit_group;" ::: "memory")

// 256-thread chunk loader: A[128][32] + B[256][32] fp32 -> one stage
__device__ __forceinline__ void ld_chunk(float* sA, float* sB,
                                         const float* Ag, const float* Bg,
                                         int kb, int tid)
{
    #pragma unroll
    for (int i = 0; i < 4; i++) {
        int f = tid + (i << 8);
        int r = f >> 3, c4 = (f & 7) << 2;
        cp16(sA + r * SROW + c4, Ag + (size_t)r * DIM + kb + c4);
    }
    #pragma unroll
    for (int i = 0; i < 8; i++) {
        int f = tid + (i << 8);
        int r = f >> 3, c4 = (f & 7) << 2;
        cp16(sB + r * SROW + c4, Bg + (size_t)r * DIM + kb + c4);
    }
    CP_COMMIT();
}

// per-warp per-thread ldmatrix address bases (byte offsets into a stage buffer)
// A: matrix idx bit0 -> +8 rows, bit1 -> +4 cols.  B: bit0 -> +4 cols, bit1 -> +8 rows.
__device__ __forceinline__ uint32_t a_lds_off(int wm, int lane) {
    int row = wm * 64 + ((lane >> 3) & 1) * 8 + (lane & 7);
    int col = ((lane >> 4) & 1) * 4;
    return (uint32_t)(row * SROW + col) * 4u;
}
__device__ __forceinline__ uint32_t b_lds_off(int wn, int lane) {
    int row = wn * 64 + ((lane >> 4) & 1) * 8 + (lane & 7);
    int col = ((lane >> 3) & 1) * 4;
    return (uint32_t)(row * SROW + col) * 4u;
}

// 8-warp compute: warp tile 64x64, acc[4][8][4], ldmatrix fragment loads
__device__ __forceinline__ void compute_stage(const float* sA, const float* sB,
                                              float acc[4][8][4],
                                              int wm, int wn, int lane)
{
    const uint32_t aAddr = smem_u32(sA) + a_lds_off(wm, lane);
    const uint32_t bAddr = smem_u32(sB) + b_lds_off(wn, lane);
    #pragma unroll
    for (int k8 = 0; k8 < 4; k8++) {
        const uint32_t kb = (uint32_t)k8 * 32u;   // 8 floats
        uint32_t a[4][4], b[8][2];
        #pragma unroll
        for (int mi = 0; mi < 4; mi++)
            ldsm4(a[mi][0], a[mi][1], a[mi][2], a[mi][3],
                  aAddr + (uint32_t)mi * (16 * SROW * 4) + kb);
        #pragma unroll
        for (int ni2 = 0; ni2 < 4; ni2++)
            ldsm4(b[2 * ni2][0], b[2 * ni2][1], b[2 * ni2 + 1][0], b[2 * ni2 + 1][1],
                  bAddr + (uint32_t)ni2 * (16 * SROW * 4) + kb);
        #pragma unroll
        for (int mi = 0; mi < 4; mi++)
            #pragma unroll
            for (int ni = 0; ni < 8; ni++)
                mma_tf32(acc[mi][ni], a[mi], b[ni]);
    }
}

// full K=512 pass over one 128x256 tile, 3-stage pipeline (256 threads)
__device__ __forceinline__ void gemm_k512(const float* Ag, const float* Bg,
                                          float* sm, float acc[4][8][4],
                                          int tid, int wm, int wn, int lane)
{
    #pragma unroll
    for (int mi = 0; mi < 4; mi++)
        #pragma unroll
        for (int ni = 0; ni < 8; ni++)
            #pragma unroll
            for (int j = 0; j < 4; j++) acc[mi][ni][j] = 0.f;

    __syncthreads();
    ld_chunk(sm + 0 * STAGE_F, sm + 0 * STAGE_F + MROWS * SROW, Ag, Bg, 0,  tid);
    ld_chunk(sm + 1 * STAGE_F, sm + 1 * STAGE_F + MROWS * SROW, Ag, Bg, 32, tid);

    for (int kt = 0; kt < 16; kt++) {
        if (kt < 15) asm volatile("cp.async.wait_group 1;" ::: "memory");
        else         asm volatile("cp.async.wait_group 0;" ::: "memory");
        __syncthreads();
        const float* buf = sm + (kt % NSTAGE) * STAGE_F;
        compute_stage(buf, buf + MROWS * SROW, acc, wm, wn, lane);
        if (kt + 2 < 16) {
            float* nb = sm + ((kt + 2) % NSTAGE) * STAGE_F;
            ld_chunk(nb, nb + MROWS * SROW, Ag, Bg, (kt + 2) * 32, tid);
        }
    }
}

// top-2 insertion with index tiebreak + dedupe
__device__ __forceinline__ void ins_min(float v, int i, float& v1, int& i1, float& v2, int& i2) {
    if (v < v1 || (v == v1 && i < i1)) {
        if (i != i1) { v2 = v1; i2 = i1; }
        v1 = v; i1 = i;
    } else if (i != i1 && (v < v2 || (v == v2 && i < i2))) { v2 = v; i2 = i; }
}
__device__ __forceinline__ void ins_max(float v, int i, float& v1, int& i1, float& v2, int& i2) {
    if (v > v1 || (v == v1 && i < i1)) {
        if (i != i1) { v2 = v1; i2 = i1; }
        v1 = v; i1 = i;
    } else if (i != i1 && (v > v2 || (v == v2 && i < i2))) { v2 = v; i2 = i; }
}

// ============================================================
// big fused kernel: 128 rows x all 8192 cols; 256 threads, 8 warps (2x4).
// LOGITS: x = D+b2 -> top2 argmax + online LSE. !LOGITS: d = esq-2D -> top2 argmin.
// ============================================================
template<bool LOGITS>
__global__ void __launch_bounds__(256, 1)
big_mma_kernel(const float* __restrict__ Ain, const float* __restrict__ B,
               const float* __restrict__ aux)
{
    extern __shared__ float sm[];
    const int tid = threadIdx.x, w = tid >> 5, lane = tid & 31;
    const int wm = w >> 2, wn = w & 3, lr = lane >> 2, lq = lane & 3;
    const int row0 = blockIdx.x * MROWS;
    const float* A = LOGITS ? (const float*)g_H : Ain;
    const float* Ag = A + (size_t)row0 * DIM;

    float v1[8], v2[8], m[8], s[8]; int i1[8], i2[8];
    #pragma unroll
    for (int st = 0; st < 8; st++) {
        v1[st] = LOGITS ? -INFINITY : INFINITY; v2[st] = v1[st];
        i1[st] = 0x7fffffff; i2[st] = 0x7fffffff;
        m[st] = -INFINITY; s[st] = 0.f;
    }

    float acc[4][8][4];
    for (int nt = 0; nt < KNUM / NROWS; nt++) {
        gemm_k512(Ag, B + (size_t)nt * NROWS * DIM, sm, acc, tid, wm, wn, lane);

        #pragma unroll
        for (int mi = 0; mi < 4; mi++)
            #pragma unroll
            for (int h = 0; h < 2; h++) {
                const int st = mi * 2 + h;
                if (LOGITS) {
                    float x16[16];
                    float mloc = -INFINITY;
                    #pragma unroll
                    for (int ni = 0; ni < 8; ni++)
                        #pragma unroll
                        for (int cc = 0; cc < 2; cc++) {
                            int col = nt * NROWS + wn * 64 + ni * 8 + lq * 2 + cc;
                            float x = acc[mi][ni][h * 2 + cc] + __ldg(&aux[col]);
                            x16[ni * 2 + cc] = x;
                            mloc = fmaxf(mloc, x);
                            if (x > v1[st]) { v2[st] = v1[st]; i2[st] = i1[st]; v1[st] = x; i1[st] = col; }
                            else if (x > v2[st]) { v2[st] = x; i2[st] = col; }
                        }
                    float mn = fmaxf(m[st], mloc);
                    float ssum = 0.f;
                    #pragma unroll
                    for (int e = 0; e < 16; e++) ssum += __expf(x16[e] - mn);
                    s[st] = fmaf(s[st], __expf(m[st] - mn), ssum);
                    m[st] = mn;
                } else {
                    #pragma unroll
                    for (int ni = 0; ni < 8; ni++)
                        #pragma unroll
                        for (int cc = 0; cc < 2; cc++) {
                            int col = nt * NROWS + wn * 64 + ni * 8 + lq * 2 + cc;
                            float d = fmaf(-2.f, acc[mi][ni][h * 2 + cc], __ldg(&g_esq[col]));
                            if (d < v1[st]) { v2[st] = v1[st]; i2[st] = i1[st]; v1[st] = d; i1[st] = col; }
                            else if (d < v2[st]) { v2[st] = d; i2[st] = col; }
                        }
                }
            }
    }

    // merge: 16 slots per row (wn x lq), rows 0..127
    __syncthreads();
    float* v1s = sm;                  float* v2s = sm + 2048;
    int*   i1s = (int*)(sm + 4096);   int*   i2s = (int*)(sm + 6144);
    float* ms  = sm + 8192;           float* ss  = sm + 10240;
    const int slot = wn * 4 + lq;
    #pragma unroll
    for (int mi = 0; mi < 4; mi++)
        #pragma unroll
        for (int h = 0; h < 2; h++) {
            int r  = wm * 64 + mi * 16 + lr + h * 8;
            int st = mi * 2 + h;
            v1s[r * 16 + slot] = v1[st]; v2s[r * 16 + slot] = v2[st];
            i1s[r * 16 + slot] = i1[st]; i2s[r * 16 + slot] = i2[st];
            if (LOGITS) { ms[r * 16 + slot] = m[st]; ss[r * 16 + slot] = s[st]; }
        }
    __syncthreads();
    if (tid < 128) {
        const int grow = row0 + tid;
        if (LOGITS) {
            float bv1 = -INFINITY, bv2 = -INFINITY; int bi1 = 0x7fffffff, bi2 = 0x7fffffff;
            float M = -INFINITY;
            #pragma unroll
            for (int k = 0; k < 16; k++) {
                ins_max(v1s[tid * 16 + k], i1s[tid * 16 + k], bv1, bi1, bv2, bi2);
                ins_max(v2s[tid * 16 + k], i2s[tid * 16 + k], bv1, bi1, bv2, bi2);
                M = fmaxf(M, ms[tid * 16 + k]);
            }
            float S = 0.f;
            #pragma unroll
            for (int k = 0; k < 16; k++) S += ss[tid * 16 + k] * __expf(ms[tid * 16 + k] - M);
            g_logi1[grow] = bi1; g_logi2[grow] = bi2;
            g_lse[grow]   = M + logf(S);
        } else {
            float bv1 = INFINITY, bv2 = INFINITY; int bi1 = 0x7fffffff, bi2 = 0x7fffffff;
            #pragma unroll
            for (int k = 0; k < 16; k++) {
                ins_min(v1s[tid * 16 + k], i1s[tid * 16 + k], bv1, bi1, bv2, bi2);
                ins_min(v2s[tid * 16 + k], i2s[tid * 16 + k], bv1, bi1, bv2, bi2);
            }
            g_meli1[grow] = bi1; g_meli2[grow] = bi2;
        }
    }
}

// ============================================================
// H = leakyrelu(X*W1^T + b1) via 3xTF32 split (fp32-equivalent precision)
// ============================================================
__device__ __forceinline__ void split_u32(uint32_t raw, uint32_t& hi, uint32_t& lo) {
    uint32_t hb = raw & 0xFFFFE000u;
    hi = hb;
    lo = __float_as_uint(__uint_as_float(raw) - __uint_as_float(hb));
}

__device__ __forceinline__ void compute_stage_3x(const float* sA, const float* sB,
                                                 float acc[4][8][4],
                                                 int wm, int wn, int lane)
{
    const uint32_t aAddr = smem_u32(sA) + a_lds_off(wm, lane);
    const uint32_t bAddr = smem_u32(sB) + b_lds_off(wn, lane);
    #pragma unroll
    for (int k8 = 0; k8 < 4; k8++) {
        const uint32_t kb = (uint32_t)k8 * 32u;
        uint32_t ar[4][4], br[8][2];
        #pragma unroll
        for (int mi = 0; mi < 4; mi++)
            ldsm4(ar[mi][0], ar[mi][1], ar[mi][2], ar[mi][3],
                  aAddr + (uint32_t)mi * (16 * SROW * 4) + kb);
        #pragma unroll
        for (int ni2 = 0; ni2 < 4; ni2++)
            ldsm4(br[2 * ni2][0], br[2 * ni2][1], br[2 * ni2 + 1][0], br[2 * ni2 + 1][1],
                  bAddr + (uint32_t)ni2 * (16 * SROW * 4) + kb);

        uint32_t ah[4][4], al[4][4], bh[8][2], bl[8][2];
        #pragma unroll
        for (int mi = 0; mi < 4; mi++)
            #pragma unroll
            for (int j = 0; j < 4; j++) split_u32(ar[mi][j], ah[mi][j], al[mi][j]);
        #pragma unroll
        for (int ni = 0; ni < 8; ni++)
            #pragma unroll
            for (int j = 0; j < 2; j++) split_u32(br[ni][j], bh[ni][j], bl[ni][j]);

        #pragma unroll
        for (int mi = 0; mi < 4; mi++)
            #pragma unroll
            for (int ni = 0; ni < 8; ni++) {
                mma_tf32(acc[mi][ni], ah[mi], bh[ni]);
                mma_tf32(acc[mi][ni], ah[mi], bl[ni]);
                mma_tf32(acc[mi][ni], al[mi], bh[ni]);
            }
    }
}

__global__ void __launch_bounds__(256, 1)
h_mma_kernel(const float* __restrict__ X, const float* __restrict__ W1,
             const float* __restrict__ b1)
{
    extern __shared__ float sm[];
    const int tid = threadIdx.x, w = tid >> 5, lane = tid & 31;
    const int wm = w >> 2, wn = w & 3, lr = lane >> 2, lq = lane & 3;
    const int row0 = blockIdx.x * MROWS;
    const int col0 = blockIdx.y * NROWS;
    const float* Ag = X  + (size_t)row0 * DIM;
    const float* Bg = W1 + (size_t)col0 * DIM;

    float acc[4][8][4];
    #pragma unroll
    for (int mi = 0; mi < 4; mi++)
        #pragma unroll
        for (int ni = 0; ni < 8; ni++)
            #pragma unroll
            for (int j = 0; j < 4; j++) acc[mi][ni][j] = 0.f;

    __syncthreads();
    ld_chunk(sm + 0 * STAGE_F, sm + 0 * STAGE_F + MROWS * SROW, Ag, Bg, 0,  tid);
    ld_chunk(sm + 1 * STAGE_F, sm + 1 * STAGE_F + MROWS * SROW, Ag, Bg, 32, tid);

    for (int kt = 0; kt < 16; kt++) {
        if (kt < 15) asm volatile("cp.async.wait_group 1;" ::: "memory");
        else         asm volatile("cp.async.wait_group 0;" ::: "memory");
        __syncthreads();
        const float* buf = sm + (kt % NSTAGE) * STAGE_F;
        compute_stage_3x(buf, buf + MROWS * SROW, acc, wm, wn, lane);
        if (kt + 2 < 16) {
            float* nb = sm + ((kt + 2) % NSTAGE) * STAGE_F;
            ld_chunk(nb, nb + MROWS * SROW, Ag, Bg, (kt + 2) * 32, tid);
        }
    }

    // epilogue: bias + leakyrelu + store float2
    #pragma unroll
    for (int mi = 0; mi < 4; mi++)
        #pragma unroll
        for (int h = 0; h < 2; h++) {
            int r = row0 + wm * 64 + mi * 16 + lr + h * 8;
            #pragma unroll
            for (int ni = 0; ni < 8; ni++) {
                int c = col0 + wn * 64 + ni * 8 + lq * 2;
                float x0 = acc[mi][ni][h * 2 + 0] + __ldg(&b1[c + 0]);
                float x1 = acc[mi][ni][h * 2 + 1] + __ldg(&b1[c + 1]);
                x0 = (x0 >= 0.f) ? x0 : NEG_SLOPE * x0;
                x1 = (x1 >= 0.f) ? x1 : NEG_SLOPE * x1;
                *(float2*)(g_H + (size_t)r * DIM + c) = make_float2(x0, x1);
            }
        }
}

// ============================================================
// ||e_k||^2
// ============================================================
__global__ void esq_kernel(const float* __restrict__ E) {
    int row  = blockIdx.x * (blockDim.x >> 5) + (threadIdx.x >> 5);
    int lane = threadIdx.x & 31;
    const float* e = E + (size_t)row * DIM;
    float s = 0.f;
    for (int c = lane; c < DIM; c += 32) { float v = e[c]; s = fmaf(v, v, s); }
    #pragma unroll
    for (int o = 16; o; o >>= 1) s += __shfl_xor_sync(0xffffffffu, s, o);
    if (lane == 0) g_esq[row] = s;
}

// ============================================================
// fp32 refine: exact re-evaluation of top-2 candidates per row
// ============================================================
__device__ __forceinline__ float dot512(const float* __restrict__ a,
                                        const float* __restrict__ b, int lane)
{
    float s = 0.f;
    #pragma unroll
    for (int t = 0; t < 4; t++) {
        float4 x = *(const float4*)(a + (lane + 32 * t) * 4);
        float4 y = *(const float4*)(b + (lane + 32 * t) * 4);
        s = fmaf(x.x, y.x, s); s = fmaf(x.y, y.y, s);
        s = fmaf(x.z, y.z, s); s = fmaf(x.w, y.w, s);
    }
    #pragma unroll
    for (int o = 16; o; o >>= 1) s += __shfl_xor_sync(0xffffffffu, s, o);
    return s;
}

__global__ void __launch_bounds__(256)
refine_kernel(const float* __restrict__ Xmel, const float* __restrict__ E,
              const float* __restrict__ W2,  const float* __restrict__ b2)
{
    const int warp = threadIdx.x >> 5, lane = threadIdx.x & 31;
    const int row = blockIdx.x * 8 + warp;
    if (row >= BSZ) return;

    const float* xr = Xmel + (size_t)row * DIM;
    const float* hr = g_H  + (size_t)row * DIM;

    int mi1 = g_meli1[row], mi2 = g_meli2[row];
    float d1 = g_esq[mi1] - 2.f * dot512(xr, E + (size_t)mi1 * DIM, lane);
    float d2 = g_esq[mi2] - 2.f * dot512(xr, E + (size_t)mi2 * DIM, lane);
    int mel_idx = (d1 < d2 || (d1 == d2 && mi1 < mi2)) ? mi1 : mi2;

    int j1 = g_logi1[row], j2 = g_logi2[row];
    float l1 = dot512(hr, W2 + (size_t)j1 * DIM, lane) + b2[j1];
    float l2 = dot512(hr, W2 + (size_t)j2 * DIM, lane) + b2[j2];
    int eeg_idx = (l1 > l2 || (l1 == l2 && j1 < j2)) ? j1 : j2;

    float t = dot512(hr, W2 + (size_t)mel_idx * DIM, lane) + b2[mel_idx];

    if (lane == 0) {
        g_loss[row]  = g_lse[row] - t;
        g_match[row] = (eeg_idx == mel_idx) ? 1.f : 0.f;
    }
}

// ============================================================
// final mean reduction
// ============================================================
__global__ void reduce_kernel(float* __restrict__ out) {
    __shared__ float sl[1024];
    __shared__ float sa[1024];
    int tid = threadIdx.x;
    float a = 0.f, b = 0.f;
    for (int i = tid; i < BSZ; i += 1024) { a += g_loss[i]; b += g_match[i]; }
    sl[tid] = a; sa[tid] = b;
    __syncthreads();
    for (int o = 512; o; o >>= 1) {
        if (tid < o) { sl[tid] += sl[tid + o]; sa[tid] += sa[tid + o]; }
        __syncthreads();
    }
    if (tid == 0) {
        out[0] = sl[0] / (float)BSZ;
        out[1] = sa[0] / (float)BSZ;
    }
}

// ============================================================
extern "C" void kernel_launch(void* const* d_in, const int* in_sizes, int n_in,
                              void* d_out, int out_size)
{
    (void)in_sizes; (void)n_in; (void)out_size;
    const float* eeg = (const float*)d_in[0];
    const float* mel = (const float*)d_in[1];
    const float* emb = (const float*)d_in[2];
    const float* W1  = (const float*)d_in[3];
    const float* b1  = (const float*)d_in[4];
    const float* W2  = (const float*)d_in[5];
    const float* b2  = (const float*)d_in[6];
    float* out = (float*)d_out;

    cudaFuncSetAttribute(big_mma_kernel<false>, cudaFuncAttributeMaxDynamicSharedMemorySize, SMEM_BYTES);
    cudaFuncSetAttribute(big_mma_kernel<true>,  cudaFuncAttributeMaxDynamicSharedMemorySize, SMEM_BYTES);
    cudaFuncSetAttribute(h_mma_kernel,          cudaFuncAttributeMaxDynamicSharedMemorySize, SMEM_BYTES);

    esq_kernel<<<KNUM / 8, 256>>>(emb);
    h_mma_kernel<<<dim3(BSZ / MROWS, DIM / NROWS), 256, SMEM_BYTES>>>(eeg, W1, b1);
    big_mma_kernel<false><<<BSZ / MROWS, 256, SMEM_BYTES>>>(mel, emb, nullptr);
    big_mma_kernel<true><<<BSZ / MROWS, 256, SMEM_BYTES>>>(nullptr, W2, b2);
    refine_kernel<<<BSZ / 8, 256>>>(mel, emb, W2, b2);
    reduce_kernel<<<1, 1024>>>(out);
}

// round 9
// speedup vs baseline: 2.0630x; 1.5476x over previous
#include <cuda_runtime.h>
#include <cuda_bf16.h>
#include <math.h>
#include <stdint.h>

#define BSZ   16384
#define DIM   512
#define KNUM  8192
#define NEG_SLOPE 0.01f

// ---- scratch (static device globals) ----
__device__ float g_esq[KNUM];
__device__ float g_H[(size_t)BSZ * DIM];      // fp32 hidden (exact, for refine)
__device__ __nv_bfloat16 g_Hb[(size_t)BSZ * DIM];   // bf16 hidden (GEMM input)
__device__ __nv_bfloat16 g_Eb[(size_t)KNUM * DIM];  // bf16 embeddings
__device__ __nv_bfloat16 g_W2b[(size_t)KNUM * DIM]; // bf16 W2
__device__ __nv_bfloat16 g_Xmb[(size_t)BSZ * DIM];  // bf16 mel input
__device__ int   g_meli1[BSZ], g_meli2[BSZ];
__device__ int   g_logi1[BSZ], g_logi2[BSZ];
__device__ float g_lse[BSZ];
__device__ float g_loss[BSZ], g_match[BSZ];

// ============================================================
// common PTX helpers
// ============================================================
__device__ __forceinline__ uint32_t smem_u32(const void* p) {
    uint32_t a;
    asm("{ .reg .u64 t; cvta.to.shared.u64 t, %1; cvt.u32.u64 %0, t; }" : "=r"(a) : "l"(p));
    return a;
}
__device__ __forceinline__ void ldsm4(uint32_t& r0, uint32_t& r1, uint32_t& r2, uint32_t& r3,
                                      uint32_t addr) {
    asm volatile("ldmatrix.sync.aligned.m8n8.x4.shared.b16 {%0,%1,%2,%3}, [%4];"
                 : "=r"(r0), "=r"(r1), "=r"(r2), "=r"(r3) : "r"(addr));
}
__device__ __forceinline__ void cp16(void* dst, const void* src) {
    unsigned d = smem_u32(dst);
    asm volatile("cp.async.cg.shared.global [%0], [%1], 16;" :: "r"(d), "l"(src));
}
#define CP_COMMIT() asm volatile("cp.async.commit_group;" ::: "memory")

// tf32 m16n8k8 (used by h_mma only)
__device__ __forceinline__ void mma_tf32(float* d, const uint32_t* a, const uint32_t* b) {
    asm volatile(
        "mma.sync.aligned.m16n8k8.row.col.f32.tf32.tf32.f32 "
        "{%0,%1,%2,%3},{%4,%5,%6,%7},{%8,%9},{%0,%1,%2,%3};"
        : "+f"(d[0]), "+f"(d[1]), "+f"(d[2]), "+f"(d[3])
        : "r"(a[0]), "r"(a[1]), "r"(a[2]), "r"(a[3]), "r"(b[0]), "r"(b[1]));
}
// bf16 m16n8k16 (big kernels)
__device__ __forceinline__ void mma_bf16(float* d, const uint32_t* a, const uint32_t* b) {
    asm volatile(
        "mma.sync.aligned.m16n8k16.row.col.f32.bf16.bf16.f32 "
        "{%0,%1,%2,%3},{%4,%5,%6,%7},{%8,%9},{%0,%1,%2,%3};"
        : "+f"(d[0]), "+f"(d[1]), "+f"(d[2]), "+f"(d[3])
        : "r"(a[0]), "r"(a[1]), "r"(a[2]), "r"(a[3]), "r"(b[0]), "r"(b[1]));
}

// ============================================================
// bf16 big-GEMM machinery: CTA 128(M) x 256(N-pass), k-chunk 64 bf16,
// 8 warps (2x4), warp tile 64x64, 3-stage cp.async ring.
// smem row = 144 B (128 B data + 16 pad) -> conflict-free ldmatrix.
// ============================================================
#define MROWS   128
#define NROWS   256
#define BROWB   144                         // bytes per smem row
#define BSTAGE  ((MROWS + NROWS) * BROWB)   // 55296 B
#define SMEM_BYTES (3 * BSTAGE)             // 165888 B (shared with h kernel)

// chunk loader: A[128][64] + B[256][64] bf16 -> one stage (256 threads, 12 cp16 each)
__device__ __forceinline__ void ld_chunk_bf(char* sbase,
                                            const __nv_bfloat16* Ag,
                                            const __nv_bfloat16* Bg,
                                            int kb, int tid)
{
    #pragma unroll
    for (int i = 0; i < 12; i++) {
        int f = tid + (i << 8);           // 0..3071
        int r = f >> 3, c = f & 7;        // row 0..383, 16B unit 0..7
        const __nv_bfloat16* src = (i < 4)
            ? (Ag + (size_t)r * DIM + kb + c * 8)
            : (Bg + (size_t)(r - 128) * DIM + kb + c * 8);
        cp16(sbase + r * BROWB + c * 16, src);
    }
    CP_COMMIT();
}

// 8-warp compute over one stage (k-chunk 64 = 4 k16 steps)
__device__ __forceinline__ void compute_stage_bf(const char* sbuf, float acc[4][8][4],
                                                 int wm, int wn, int lane)
{
    const uint32_t sb = smem_u32(sbuf);
    const uint32_t aAddr = sb + (uint32_t)((wm * 64 + (lane & 7) + ((lane >> 3) & 1) * 8) * BROWB
                                           + ((lane >> 4) & 1) * 16);
    const uint32_t bAddr = sb + (uint32_t)((128 + wn * 64 + (lane & 7) + ((lane >> 4) & 1) * 8) * BROWB
                                           + ((lane >> 3) & 1) * 16);
    #pragma unroll
    for (int k16 = 0; k16 < 4; k16++) {
        const uint32_t kb = (uint32_t)k16 * 32u;   // 16 bf16 = 32 B
        uint32_t a[4][4], b[8][2];
        #pragma unroll
        for (int mi = 0; mi < 4; mi++)
            ldsm4(a[mi][0], a[mi][1], a[mi][2], a[mi][3],
                  aAddr + (uint32_t)mi * (16 * BROWB) + kb);
        #pragma unroll
        for (int p = 0; p < 4; p++)
            ldsm4(b[2 * p][0], b[2 * p][1], b[2 * p + 1][0], b[2 * p + 1][1],
                  bAddr + (uint32_t)p * (16 * BROWB) + kb);
        #pragma unroll
        for (int mi = 0; mi < 4; mi++)
            #pragma unroll
            for (int ni = 0; ni < 8; ni++)
                mma_bf16(acc[mi][ni], a[mi], b[ni]);
    }
}

// full K=512 pass over one 128x256 tile (8 stages, 3-stage ring)
__device__ __forceinline__ void gemm_k512_bf(const __nv_bfloat16* Ag, const __nv_bfloat16* Bg,
                                             char* sm, float acc[4][8][4],
                                             int tid, int wm, int wn, int lane)
{
    #pragma unroll
    for (int mi = 0; mi < 4; mi++)
        #pragma unroll
        for (int ni = 0; ni < 8; ni++)
            #pragma unroll
            for (int j = 0; j < 4; j++) acc[mi][ni][j] = 0.f;

    __syncthreads();
    ld_chunk_bf(sm + 0 * BSTAGE, Ag, Bg, 0,  tid);
    ld_chunk_bf(sm + 1 * BSTAGE, Ag, Bg, 64, tid);

    for (int kt = 0; kt < 8; kt++) {
        if (kt < 7) asm volatile("cp.async.wait_group 1;" ::: "memory");
        else        asm volatile("cp.async.wait_group 0;" ::: "memory");
        __syncthreads();
        compute_stage_bf(sm + (kt % 3) * BSTAGE, acc, wm, wn, lane);
        if (kt + 2 < 8)
            ld_chunk_bf(sm + ((kt + 2) % 3) * BSTAGE, Ag, Bg, (kt + 2) * 64, tid);
    }
}

// top-2 insertion with index tiebreak + dedupe
__device__ __forceinline__ void ins_min(float v, int i, float& v1, int& i1, float& v2, int& i2) {
    if (v < v1 || (v == v1 && i < i1)) {
        if (i != i1) { v2 = v1; i2 = i1; }
        v1 = v; i1 = i;
    } else if (i != i1 && (v < v2 || (v == v2 && i < i2))) { v2 = v; i2 = i; }
}
__device__ __forceinline__ void ins_max(float v, int i, float& v1, int& i1, float& v2, int& i2) {
    if (v > v1 || (v == v1 && i < i1)) {
        if (i != i1) { v2 = v1; i2 = i1; }
        v1 = v; i1 = i;
    } else if (i != i1 && (v > v2 || (v == v2 && i < i2))) { v2 = v; i2 = i; }
}

// ============================================================
// big fused kernel (bf16): 128 rows x all 8192 cols; 256 threads, 8 warps.
// LOGITS: x = D+b2 -> top2 argmax + online LSE. !LOGITS: d = esq-2D -> top2 argmin.
// ============================================================
template<bool LOGITS>
__global__ void __launch_bounds__(256, 1)
big_mma_kernel(const __nv_bfloat16* __restrict__ Ain, const __nv_bfloat16* __restrict__ B,
               const float* __restrict__ aux)
{
    extern __shared__ float smf[];
    char* sm = (char*)smf;
    const int tid = threadIdx.x, w = tid >> 5, lane = tid & 31;
    const int wm = w >> 2, wn = w & 3, lr = lane >> 2, lq = lane & 3;
    const int row0 = blockIdx.x * MROWS;
    const __nv_bfloat16* A = LOGITS ? (const __nv_bfloat16*)g_Hb : Ain;   // <-- fixed (R8 passed nullptr)
    const __nv_bfloat16* Ag = A + (size_t)row0 * DIM;

    float v1[8], v2[8], m[8], s[8]; int i1[8], i2[8];
    #pragma unroll
    for (int st = 0; st < 8; st++) {
        v1[st] = LOGITS ? -INFINITY : INFINITY; v2[st] = v1[st];
        i1[st] = 0x7fffffff; i2[st] = 0x7fffffff;
        m[st] = -INFINITY; s[st] = 0.f;
    }

    float acc[4][8][4];
    for (int nt = 0; nt < KNUM / NROWS; nt++) {
        gemm_k512_bf(Ag, B + (size_t)nt * NROWS * DIM, sm, acc, tid, wm, wn, lane);

        #pragma unroll
        for (int mi = 0; mi < 4; mi++)
            #pragma unroll
            for (int h = 0; h < 2; h++) {
                const int st = mi * 2 + h;
                if (LOGITS) {
                    float x16[16];
                    float mloc = -INFINITY;
                    #pragma unroll
                    for (int ni = 0; ni < 8; ni++)
                        #pragma unroll
                        for (int cc = 0; cc < 2; cc++) {
                            int col = nt * NROWS + wn * 64 + ni * 8 + lq * 2 + cc;
                            float x = acc[mi][ni][h * 2 + cc] + __ldg(&aux[col]);
                            x16[ni * 2 + cc] = x;
                            mloc = fmaxf(mloc, x);
                            if (x > v1[st]) { v2[st] = v1[st]; i2[st] = i1[st]; v1[st] = x; i1[st] = col; }
                            else if (x > v2[st]) { v2[st] = x; i2[st] = col; }
                        }
                    float mn = fmaxf(m[st], mloc);
                    float ssum = 0.f;
                    #pragma unroll
                    for (int e = 0; e < 16; e++) ssum += __expf(x16[e] - mn);
                    s[st] = fmaf(s[st], __expf(m[st] - mn), ssum);
                    m[st] = mn;
                } else {
                    #pragma unroll
                    for (int ni = 0; ni < 8; ni++)
                        #pragma unroll
                        for (int cc = 0; cc < 2; cc++) {
                            int col = nt * NROWS + wn * 64 + ni * 8 + lq * 2 + cc;
                            float d = fmaf(-2.f, acc[mi][ni][h * 2 + cc], __ldg(&g_esq[col]));
                            if (d < v1[st]) { v2[st] = v1[st]; i2[st] = i1[st]; v1[st] = d; i1[st] = col; }
                            else if (d < v2[st]) { v2[st] = d; i2[st] = col; }
                        }
                }
            }
    }

    // merge: 16 slots per row (wn x lq), rows 0..127
    __syncthreads();
    float* v1s = smf;                  float* v2s = smf + 2048;
    int*   i1s = (int*)(smf + 4096);   int*   i2s = (int*)(smf + 6144);
    float* ms  = smf + 8192;           float* ss  = smf + 10240;
    const int slot = wn * 4 + lq;
    #pragma unroll
    for (int mi = 0; mi < 4; mi++)
        #pragma unroll
        for (int h = 0; h < 2; h++) {
            int r  = wm * 64 + mi * 16 + lr + h * 8;
            int st = mi * 2 + h;
            v1s[r * 16 + slot] = v1[st]; v2s[r * 16 + slot] = v2[st];
            i1s[r * 16 + slot] = i1[st]; i2s[r * 16 + slot] = i2[st];
            if (LOGITS) { ms[r * 16 + slot] = m[st]; ss[r * 16 + slot] = s[st]; }
        }
    __syncthreads();
    if (tid < 128) {
        const int grow = row0 + tid;
        if (LOGITS) {
            float bv1 = -INFINITY, bv2 = -INFINITY; int bi1 = 0x7fffffff, bi2 = 0x7fffffff;
            float M = -INFINITY;
            #pragma unroll
            for (int k = 0; k < 16; k++) {
                ins_max(v1s[tid * 16 + k], i1s[tid * 16 + k], bv1, bi1, bv2, bi2);
                ins_max(v2s[tid * 16 + k], i2s[tid * 16 + k], bv1, bi1, bv2, bi2);
                M = fmaxf(M, ms[tid * 16 + k]);
            }
            float S = 0.f;
            #pragma unroll
            for (int k = 0; k < 16; k++) S += ss[tid * 16 + k] * __expf(ms[tid * 16 + k] - M);
            g_logi1[grow] = bi1; g_logi2[grow] = bi2;
            g_lse[grow]   = M + logf(S);
        } else {
            float bv1 = INFINITY, bv2 = INFINITY; int bi1 = 0x7fffffff, bi2 = 0x7fffffff;
            #pragma unroll
            for (int k = 0; k < 16; k++) {
                ins_min(v1s[tid * 16 + k], i1s[tid * 16 + k], bv1, bi1, bv2, bi2);
                ins_min(v2s[tid * 16 + k], i2s[tid * 16 + k], bv1, bi1, bv2, bi2);
            }
            g_meli1[grow] = bi1; g_meli2[grow] = bi2;
        }
    }
}

// ============================================================
// fp32->bf16 cast kernel (E, W2, Xmel)
// ============================================================
__global__ void conv_bf16(const float4* __restrict__ in, uint2* __restrict__ out, int n4) {
    int i = blockIdx.x * blockDim.x + threadIdx.x;
    if (i < n4) {
        float4 v = in[i];
        __nv_bfloat162 a = __floats2bfloat162_rn(v.x, v.y);
        __nv_bfloat162 b = __floats2bfloat162_rn(v.z, v.w);
        uint2 u;
        u.x = *(uint32_t*)&a;
        u.y = *(uint32_t*)&b;
        out[i] = u;
    }
}

// ============================================================
// h kernel: fp32-accurate H via 3xTF32 split,
// epilogue additionally emits bf16 copy g_Hb.
// ============================================================
#define SROW    36
#define STAGE_F ((MROWS + NROWS) * SROW)

__device__ __forceinline__ void ld_chunk_f32(float* sA, float* sB,
                                             const float* Ag, const float* Bg,
                                             int kb, int tid)
{
    #pragma unroll
    for (int i = 0; i < 4; i++) {
        int f = tid + (i << 8);
        int r = f >> 3, c4 = (f & 7) << 2;
        cp16(sA + r * SROW + c4, Ag + (size_t)r * DIM + kb + c4);
    }
    #pragma unroll
    for (int i = 0; i < 8; i++) {
        int f = tid + (i << 8);
        int r = f >> 3, c4 = (f & 7) << 2;
        cp16(sB + r * SROW + c4, Bg + (size_t)r * DIM + kb + c4);
    }
    CP_COMMIT();
}

__device__ __forceinline__ uint32_t a_lds_off(int wm, int lane) {
    int row = wm * 64 + ((lane >> 3) & 1) * 8 + (lane & 7);
    int col = ((lane >> 4) & 1) * 4;
    return (uint32_t)(row * SROW + col) * 4u;
}
__device__ __forceinline__ uint32_t b_lds_off(int wn, int lane) {
    int row = wn * 64 + ((lane >> 4) & 1) * 8 + (lane & 7);
    int col = ((lane >> 3) & 1) * 4;
    return (uint32_t)(row * SROW + col) * 4u;
}

__device__ __forceinline__ void split_u32(uint32_t raw, uint32_t& hi, uint32_t& lo) {
    uint32_t hb = raw & 0xFFFFE000u;
    hi = hb;
    lo = __float_as_uint(__uint_as_float(raw) - __uint_as_float(hb));
}

__device__ __forceinline__ void compute_stage_3x(const float* sA, const float* sB,
                                                 float acc[4][8][4],
                                                 int wm, int wn, int lane)
{
    const uint32_t aAddr = smem_u32(sA) + a_lds_off(wm, lane);
    const uint32_t bAddr = smem_u32(sB) + b_lds_off(wn, lane);
    #pragma unroll
    for (int k8 = 0; k8 < 4; k8++) {
        const uint32_t kb = (uint32_t)k8 * 32u;
        uint32_t ar[4][4], br[8][2];
        #pragma unroll
        for (int mi = 0; mi < 4; mi++)
            ldsm4(ar[mi][0], ar[mi][1], ar[mi][2], ar[mi][3],
                  aAddr + (uint32_t)mi * (16 * SROW * 4) + kb);
        #pragma unroll
        for (int ni2 = 0; ni2 < 4; ni2++)
            ldsm4(br[2 * ni2][0], br[2 * ni2][1], br[2 * ni2 + 1][0], br[2 * ni2 + 1][1],
                  bAddr + (uint32_t)ni2 * (16 * SROW * 4) + kb);

        uint32_t ah[4][4], al[4][4], bh[8][2], bl[8][2];
        #pragma unroll
        for (int mi = 0; mi < 4; mi++)
            #pragma unroll
            for (int j = 0; j < 4; j++) split_u32(ar[mi][j], ah[mi][j], al[mi][j]);
        #pragma unroll
        for (int ni = 0; ni < 8; ni++)
            #pragma unroll
            for (int j = 0; j < 2; j++) split_u32(br[ni][j], bh[ni][j], bl[ni][j]);

        #pragma unroll
        for (int mi = 0; mi < 4; mi++)
            #pragma unroll
            for (int ni = 0; ni < 8; ni++) {
                mma_tf32(acc[mi][ni], ah[mi], bh[ni]);
                mma_tf32(acc[mi][ni], ah[mi], bl[ni]);
                mma_tf32(acc[mi][ni], al[mi], bh[ni]);
            }
    }
}

__global__ void __launch_bounds__(256, 1)
h_mma_kernel(const float* __restrict__ X, const float* __restrict__ W1,
             const float* __restrict__ b1)
{
    extern __shared__ float smf[];
    const int tid = threadIdx.x, w = tid >> 5, lane = tid & 31;
    const int wm = w >> 2, wn = w & 3, lr = lane >> 2, lq = lane & 3;
    const int row0 = blockIdx.x * MROWS;
    const int col0 = blockIdx.y * NROWS;
    const float* Ag = X  + (size_t)row0 * DIM;
    const float* Bg = W1 + (size_t)col0 * DIM;

    float acc[4][8][4];
    #pragma unroll
    for (int mi = 0; mi < 4; mi++)
        #pragma unroll
        for (int ni = 0; ni < 8; ni++)
            #pragma unroll
            for (int j = 0; j < 4; j++) acc[mi][ni][j] = 0.f;

    __syncthreads();
    ld_chunk_f32(smf + 0 * STAGE_F, smf + 0 * STAGE_F + MROWS * SROW, Ag, Bg, 0,  tid);
    ld_chunk_f32(smf + 1 * STAGE_F, smf + 1 * STAGE_F + MROWS * SROW, Ag, Bg, 32, tid);

    for (int kt = 0; kt < 16; kt++) {
        if (kt < 15) asm volatile("cp.async.wait_group 1;" ::: "memory");
        else         asm volatile("cp.async.wait_group 0;" ::: "memory");
        __syncthreads();
        const float* buf = smf + (kt % 3) * STAGE_F;
        compute_stage_3x(buf, buf + MROWS * SROW, acc, wm, wn, lane);
        if (kt + 2 < 16) {
            float* nb = smf + ((kt + 2) % 3) * STAGE_F;
            ld_chunk_f32(nb, nb + MROWS * SROW, Ag, Bg, (kt + 2) * 32, tid);
        }
    }

    #pragma unroll
    for (int mi = 0; mi < 4; mi++)
        #pragma unroll
        for (int h = 0; h < 2; h++) {
            int r = row0 + wm * 64 + mi * 16 + lr + h * 8;
            #pragma unroll
            for (int ni = 0; ni < 8; ni++) {
                int c = col0 + wn * 64 + ni * 8 + lq * 2;
                float x0 = acc[mi][ni][h * 2 + 0] + __ldg(&b1[c + 0]);
                float x1 = acc[mi][ni][h * 2 + 1] + __ldg(&b1[c + 1]);
                x0 = (x0 >= 0.f) ? x0 : NEG_SLOPE * x0;
                x1 = (x1 >= 0.f) ? x1 : NEG_SLOPE * x1;
                *(float2*)(g_H + (size_t)r * DIM + c) = make_float2(x0, x1);
                __nv_bfloat162 hb = __floats2bfloat162_rn(x0, x1);
                *(uint32_t*)(g_Hb + (size_t)r * DIM + c) = *(uint32_t*)&hb;
            }
        }
}

// ============================================================
// ||e_k||^2
// ============================================================
__global__ void esq_kernel(const float* __restrict__ E) {
    int row  = blockIdx.x * (blockDim.x >> 5) + (threadIdx.x >> 5);
    int lane = threadIdx.x & 31;
    const float* e = E + (size_t)row * DIM;
    float s = 0.f;
    for (int c = lane; c < DIM; c += 32) { float v = e[c]; s = fmaf(v, v, s); }
    #pragma unroll
    for (int o = 16; o; o >>= 1) s += __shfl_xor_sync(0xffffffffu, s, o);
    if (lane == 0) g_esq[row] = s;
}

// ============================================================
// fp32 refine: exact re-evaluation of top-2 candidates per row
// ============================================================
__device__ __forceinline__ float dot512(const float* __restrict__ a,
                                        const float* __restrict__ b, int lane)
{
    float s = 0.f;
    #pragma unroll
    for (int t = 0; t < 4; t++) {
        float4 x = *(const float4*)(a + (lane + 32 * t) * 4);
        float4 y = *(const float4*)(b + (lane + 32 * t) * 4);
        s = fmaf(x.x, y.x, s); s = fmaf(x.y, y.y, s);
        s = fmaf(x.z, y.z, s); s = fmaf(x.w, y.w, s);
    }
    #pragma unroll
    for (int o = 16; o; o >>= 1) s += __shfl_xor_sync(0xffffffffu, s, o);
    return s;
}

__global__ void __launch_bounds__(256)
refine_kernel(const float* __restrict__ Xmel, const float* __restrict__ E,
              const float* __restrict__ W2,  const float* __restrict__ b2)
{
    const int warp = threadIdx.x >> 5, lane = threadIdx.x & 31;
    const int row = blockIdx.x * 8 + warp;
    if (row >= BSZ) return;

    const float* xr = Xmel + (size_t)row * DIM;
    const float* hr = g_H  + (size_t)row * DIM;

    int mi1 = g_meli1[row], mi2 = g_meli2[row];
    float d1 = g_esq[mi1] - 2.f * dot512(xr, E + (size_t)mi1 * DIM, lane);
    float d2 = g_esq[mi2] - 2.f * dot512(xr, E + (size_t)mi2 * DIM, lane);
    int mel_idx = (d1 < d2 || (d1 == d2 && mi1 < mi2)) ? mi1 : mi2;

    int j1 = g_logi1[row], j2 = g_logi2[row];
    float l1 = dot512(hr, W2 + (size_t)j1 * DIM, lane) + b2[j1];
    float l2 = dot512(hr, W2 + (size_t)j2 * DIM, lane) + b2[j2];
    int eeg_idx = (l1 > l2 || (l1 == l2 && j1 < j2)) ? j1 : j2;

    float t = dot512(hr, W2 + (size_t)mel_idx * DIM, lane) + b2[mel_idx];

    if (lane == 0) {
        g_loss[row]  = g_lse[row] - t;
        g_match[row] = (eeg_idx == mel_idx) ? 1.f : 0.f;
    }
}

// ============================================================
// final mean reduction
// ============================================================
__global__ void reduce_kernel(float* __restrict__ out) {
    __shared__ float sl[1024];
    __shared__ float sa[1024];
    int tid = threadIdx.x;
    float a = 0.f, b = 0.f;
    for (int i = tid; i < BSZ; i += 1024) { a += g_loss[i]; b += g_match[i]; }
    sl[tid] = a; sa[tid] = b;
    __syncthreads();
    for (int o = 512; o; o >>= 1) {
        if (tid < o) { sl[tid] += sl[tid + o]; sa[tid] += sa[tid + o]; }
        __syncthreads();
    }
    if (tid == 0) {
        out[0] = sl[0] / (float)BSZ;
        out[1] = sa[0] / (float)BSZ;
    }
}

// ============================================================
extern "C" void kernel_launch(void* const* d_in, const int* in_sizes, int n_in,
                              void* d_out, int out_size)
{
    (void)in_sizes; (void)n_in; (void)out_size;
    const float* eeg = (const float*)d_in[0];
    const float* mel = (const float*)d_in[1];
    const float* emb = (const float*)d_in[2];
    const float* W1  = (const float*)d_in[3];
    const float* b1  = (const float*)d_in[4];
    const float* W2  = (const float*)d_in[5];
    const float* b2  = (const float*)d_in[6];
    float* out = (float*)d_out;

    cudaFuncSetAttribute(big_mma_kernel<false>, cudaFuncAttributeMaxDynamicSharedMemorySize, SMEM_BYTES);
    cudaFuncSetAttribute(big_mma_kernel<true>,  cudaFuncAttributeMaxDynamicSharedMemorySize, SMEM_BYTES);
    cudaFuncSetAttribute(h_mma_kernel,          cudaFuncAttributeMaxDynamicSharedMemorySize, SMEM_BYTES);

    __nv_bfloat16 *dEb, *dW2b, *dXmb;
    cudaGetSymbolAddress((void**)&dEb,  g_Eb);
    cudaGetSymbolAddress((void**)&dW2b, g_W2b);
    cudaGetSymbolAddress((void**)&dXmb, g_Xmb);

    esq_kernel<<<KNUM / 8, 256>>>(emb);
    conv_bf16<<<(KNUM * DIM / 4 + 255) / 256, 256>>>((const float4*)emb, (uint2*)dEb,  KNUM * DIM / 4);
    conv_bf16<<<(KNUM * DIM / 4 + 255) / 256, 256>>>((const float4*)W2,  (uint2*)dW2b, KNUM * DIM / 4);
    conv_bf16<<<(BSZ * DIM / 4 + 255) / 256, 256>>>((const float4*)mel, (uint2*)dXmb, BSZ * DIM / 4);
    h_mma_kernel<<<dim3(BSZ / MROWS, DIM / NROWS), 256, SMEM_BYTES>>>(eeg, W1, b1);
    big_mma_kernel<false><<<BSZ / MROWS, 256, SMEM_BYTES>>>(dXmb, dEb, nullptr);
    big_mma_kernel<true><<<BSZ / MROWS, 256, SMEM_BYTES>>>(nullptr, dW2b, b2);
    refine_kernel<<<BSZ / 8, 256>>>(mel, emb, W2, b2);
    reduce_kernel<<<1, 1024>>>(out);
}

// round 10
// speedup vs baseline: 2.0891x; 1.0126x over previous
#include <cuda_runtime.h>
#include <cuda_bf16.h>
#include <math.h>
#include <stdint.h>

#define BSZ   16384
#define DIM   512
#define KNUM  8192
#define NEG_SLOPE 0.01f

// ---- scratch (static device globals) ----
__device__ float g_esq[KNUM];
__device__ float g_H[(size_t)BSZ * DIM];            // fp32 hidden (exact, for refine)
__device__ __nv_bfloat16 g_Hb[(size_t)BSZ * DIM];   // bf16 hidden (GEMM input)
__device__ __nv_bfloat16 g_Eb[(size_t)KNUM * DIM];  // bf16 embeddings
__device__ __nv_bfloat16 g_W2b[(size_t)KNUM * DIM]; // bf16 W2
__device__ __nv_bfloat16 g_Xmb[(size_t)BSZ * DIM];  // bf16 mel input
__device__ __nv_bfloat16 g_Xeh[(size_t)BSZ * DIM];  // eeg hi/lo split
__device__ __nv_bfloat16 g_Xel[(size_t)BSZ * DIM];
__device__ __nv_bfloat16 g_W1h[(size_t)DIM * DIM];  // W1 hi/lo split
__device__ __nv_bfloat16 g_W1l[(size_t)DIM * DIM];
__device__ int   g_meli1[BSZ], g_meli2[BSZ];
__device__ int   g_logi1[BSZ], g_logi2[BSZ];
__device__ float g_lse[BSZ];
__device__ float g_loss[BSZ], g_match[BSZ];

// ============================================================
// common PTX helpers
// ============================================================
__device__ __forceinline__ uint32_t smem_u32(const void* p) {
    uint32_t a;
    asm("{ .reg .u64 t; cvta.to.shared.u64 t, %1; cvt.u32.u64 %0, t; }" : "=r"(a) : "l"(p));
    return a;
}
__device__ __forceinline__ void ldsm4(uint32_t& r0, uint32_t& r1, uint32_t& r2, uint32_t& r3,
                                      uint32_t addr) {
    asm volatile("ldmatrix.sync.aligned.m8n8.x4.shared.b16 {%0,%1,%2,%3}, [%4];"
                 : "=r"(r0), "=r"(r1), "=r"(r2), "=r"(r3) : "r"(addr));
}
__device__ __forceinline__ void cp16(void* dst, const void* src) {
    unsigned d = smem_u32(dst);
    asm volatile("cp.async.cg.shared.global [%0], [%1], 16;" :: "r"(d), "l"(src));
}
#define CP_COMMIT() asm volatile("cp.async.commit_group;" ::: "memory")

// bf16 m16n8k16
__device__ __forceinline__ void mma_bf16(float* d, const uint32_t* a, const uint32_t* b) {
    asm volatile(
        "mma.sync.aligned.m16n8k16.row.col.f32.bf16.bf16.f32 "
        "{%0,%1,%2,%3},{%4,%5,%6,%7},{%8,%9},{%0,%1,%2,%3};"
        : "+f"(d[0]), "+f"(d[1]), "+f"(d[2]), "+f"(d[3])
        : "r"(a[0]), "r"(a[1]), "r"(a[2]), "r"(a[3]), "r"(b[0]), "r"(b[1]));
}

// ============================================================
// bf16 big-GEMM machinery: CTA 128(M) x 256(N-pass), k-chunk 64 bf16,
// 8 warps (2x4), warp tile 64x64, 3-stage cp.async ring.
// smem row = 144 B (128 B data + 16 pad) -> conflict-free ldmatrix.
// ============================================================
#define MROWS   128
#define NROWS   256
#define BROWB   144
#define BSTAGE  ((MROWS + NROWS) * BROWB)   // 55296 B
#define SMEM_BYTES (3 * BSTAGE)             // 165888 B

__device__ __forceinline__ void ld_chunk_bf(char* sbase,
                                            const __nv_bfloat16* Ag,
                                            const __nv_bfloat16* Bg,
                                            int kb, int tid)
{
    #pragma unroll
    for (int i = 0; i < 12; i++) {
        int f = tid + (i << 8);
        int r = f >> 3, c = f & 7;
        const __nv_bfloat16* src = (i < 4)
            ? (Ag + (size_t)r * DIM + kb + c * 8)
            : (Bg + (size_t)(r - 128) * DIM + kb + c * 8);
        cp16(sbase + r * BROWB + c * 16, src);
    }
    CP_COMMIT();
}

__device__ __forceinline__ void compute_stage_bf(const char* sbuf, float acc[4][8][4],
                                                 int wm, int wn, int lane)
{
    const uint32_t sb = smem_u32(sbuf);
    const uint32_t aAddr = sb + (uint32_t)((wm * 64 + (lane & 7) + ((lane >> 3) & 1) * 8) * BROWB
                                           + ((lane >> 4) & 1) * 16);
    const uint32_t bAddr = sb + (uint32_t)((128 + wn * 64 + (lane & 7) + ((lane >> 4) & 1) * 8) * BROWB
                                           + ((lane >> 3) & 1) * 16);
    #pragma unroll
    for (int k16 = 0; k16 < 4; k16++) {
        const uint32_t kb = (uint32_t)k16 * 32u;
        uint32_t a[4][4], b[8][2];
        #pragma unroll
        for (int mi = 0; mi < 4; mi++)
            ldsm4(a[mi][0], a[mi][1], a[mi][2], a[mi][3],
                  aAddr + (uint32_t)mi * (16 * BROWB) + kb);
        #pragma unroll
        for (int p = 0; p < 4; p++)
            ldsm4(b[2 * p][0], b[2 * p][1], b[2 * p + 1][0], b[2 * p + 1][1],
                  bAddr + (uint32_t)p * (16 * BROWB) + kb);
        #pragma unroll
        for (int mi = 0; mi < 4; mi++)
            #pragma unroll
            for (int ni = 0; ni < 8; ni++)
                mma_bf16(acc[mi][ni], a[mi], b[ni]);
    }
}

__device__ __forceinline__ void gemm_k512_bf(const __nv_bfloat16* Ag, const __nv_bfloat16* Bg,
                                             char* sm, float acc[4][8][4],
                                             int tid, int wm, int wn, int lane)
{
    #pragma unroll
    for (int mi = 0; mi < 4; mi++)
        #pragma unroll
        for (int ni = 0; ni < 8; ni++)
            #pragma unroll
            for (int j = 0; j < 4; j++) acc[mi][ni][j] = 0.f;

    __syncthreads();
    ld_chunk_bf(sm + 0 * BSTAGE, Ag, Bg, 0,  tid);
    ld_chunk_bf(sm + 1 * BSTAGE, Ag, Bg, 64, tid);

    for (int kt = 0; kt < 8; kt++) {
        if (kt < 7) asm volatile("cp.async.wait_group 1;" ::: "memory");
        else        asm volatile("cp.async.wait_group 0;" ::: "memory");
        __syncthreads();
        compute_stage_bf(sm + (kt % 3) * BSTAGE, acc, wm, wn, lane);
        if (kt + 2 < 8)
            ld_chunk_bf(sm + ((kt + 2) % 3) * BSTAGE, Ag, Bg, (kt + 2) * 64, tid);
    }
}

// top-2 insertion with index tiebreak + dedupe
__device__ __forceinline__ void ins_min(float v, int i, float& v1, int& i1, float& v2, int& i2) {
    if (v < v1 || (v == v1 && i < i1)) {
        if (i != i1) { v2 = v1; i2 = i1; }
        v1 = v; i1 = i;
    } else if (i != i1 && (v < v2 || (v == v2 && i < i2))) { v2 = v; i2 = i; }
}
__device__ __forceinline__ void ins_max(float v, int i, float& v1, int& i1, float& v2, int& i2) {
    if (v > v1 || (v == v1 && i < i1)) {
        if (i != i1) { v2 = v1; i2 = i1; }
        v1 = v; i1 = i;
    } else if (i != i1 && (v > v2 || (v == v2 && i < i2))) { v2 = v; i2 = i; }
}

// ============================================================
// MERGED big fused kernel: grid 256. bx<128 -> mel argmin block bx;
// bx>=128 -> logits block bx-128 (reads g_Hb written by h_mma_kernel).
// ============================================================
__global__ void __launch_bounds__(256, 1)
big_mma_all(const __nv_bfloat16* __restrict__ Amel,
            const __nv_bfloat16* __restrict__ Bmel,
            const __nv_bfloat16* __restrict__ Blog,
            const float* __restrict__ b2)
{
    extern __shared__ float smf[];
    char* sm = (char*)smf;
    const int tid = threadIdx.x, w = tid >> 5, lane = tid & 31;
    const int wm = w >> 2, wn = w & 3, lr = lane >> 2, lq = lane & 3;
    const bool LOGITS = (blockIdx.x >= 128);
    const int row0 = (blockIdx.x & 127) * MROWS;
    const __nv_bfloat16* A = LOGITS ? (const __nv_bfloat16*)g_Hb : Amel;
    const __nv_bfloat16* B = LOGITS ? Blog : Bmel;
    const __nv_bfloat16* Ag = A + (size_t)row0 * DIM;

    float v1[8], v2[8], m[8], s[8]; int i1[8], i2[8];
    #pragma unroll
    for (int st = 0; st < 8; st++) {
        v1[st] = LOGITS ? -INFINITY : INFINITY; v2[st] = v1[st];
        i1[st] = 0x7fffffff; i2[st] = 0x7fffffff;
        m[st] = -INFINITY; s[st] = 0.f;
    }

    float acc[4][8][4];
    for (int nt = 0; nt < KNUM / NROWS; nt++) {
        gemm_k512_bf(Ag, B + (size_t)nt * NROWS * DIM, sm, acc, tid, wm, wn, lane);

        #pragma unroll
        for (int mi = 0; mi < 4; mi++)
            #pragma unroll
            for (int h = 0; h < 2; h++) {
                const int st = mi * 2 + h;
                if (LOGITS) {
                    float x16[16];
                    float mloc = -INFINITY;
                    #pragma unroll
                    for (int ni = 0; ni < 8; ni++)
                        #pragma unroll
                        for (int cc = 0; cc < 2; cc++) {
                            int col = nt * NROWS + wn * 64 + ni * 8 + lq * 2 + cc;
                            float x = acc[mi][ni][h * 2 + cc] + __ldg(&b2[col]);
                            x16[ni * 2 + cc] = x;
                            mloc = fmaxf(mloc, x);
                            if (x > v1[st]) { v2[st] = v1[st]; i2[st] = i1[st]; v1[st] = x; i1[st] = col; }
                            else if (x > v2[st]) { v2[st] = x; i2[st] = col; }
                        }
                    float mn = fmaxf(m[st], mloc);
                    float ssum = 0.f;
                    #pragma unroll
                    for (int e = 0; e < 16; e++) ssum += __expf(x16[e] - mn);
                    s[st] = fmaf(s[st], __expf(m[st] - mn), ssum);
                    m[st] = mn;
                } else {
                    #pragma unroll
                    for (int ni = 0; ni < 8; ni++)
                        #pragma unroll
                        for (int cc = 0; cc < 2; cc++) {
                            int col = nt * NROWS + wn * 64 + ni * 8 + lq * 2 + cc;
                            float d = fmaf(-2.f, acc[mi][ni][h * 2 + cc], __ldg(&g_esq[col]));
                            if (d < v1[st]) { v2[st] = v1[st]; i2[st] = i1[st]; v1[st] = d; i1[st] = col; }
                            else if (d < v2[st]) { v2[st] = d; i2[st] = col; }
                        }
                }
            }
    }

    // merge: 16 slots per row (wn x lq), rows 0..127
    __syncthreads();
    float* v1s = smf;                  float* v2s = smf + 2048;
    int*   i1s = (int*)(smf + 4096);   int*   i2s = (int*)(smf + 6144);
    float* ms  = smf + 8192;           float* ss  = smf + 10240;
    const int slot = wn * 4 + lq;
    #pragma unroll
    for (int mi = 0; mi < 4; mi++)
        #pragma unroll
        for (int h = 0; h < 2; h++) {
            int r  = wm * 64 + mi * 16 + lr + h * 8;
            int st = mi * 2 + h;
            v1s[r * 16 + slot] = v1[st]; v2s[r * 16 + slot] = v2[st];
            i1s[r * 16 + slot] = i1[st]; i2s[r * 16 + slot] = i2[st];
            if (LOGITS) { ms[r * 16 + slot] = m[st]; ss[r * 16 + slot] = s[st]; }
        }
    __syncthreads();
    if (tid < 128) {
        const int grow = row0 + tid;
        if (LOGITS) {
            float bv1 = -INFINITY, bv2 = -INFINITY; int bi1 = 0x7fffffff, bi2 = 0x7fffffff;
            float M = -INFINITY;
            #pragma unroll
            for (int k = 0; k < 16; k++) {
                ins_max(v1s[tid * 16 + k], i1s[tid * 16 + k], bv1, bi1, bv2, bi2);
                ins_max(v2s[tid * 16 + k], i2s[tid * 16 + k], bv1, bi1, bv2, bi2);
                M = fmaxf(M, ms[tid * 16 + k]);
            }
            float S = 0.f;
            #pragma unroll
            for (int k = 0; k < 16; k++) S += ss[tid * 16 + k] * __expf(ms[tid * 16 + k] - M);
            g_logi1[grow] = bi1; g_logi2[grow] = bi2;
            g_lse[grow]   = M + logf(S);
        } else {
            float bv1 = INFINITY, bv2 = INFINITY; int bi1 = 0x7fffffff, bi2 = 0x7fffffff;
            #pragma unroll
            for (int k = 0; k < 16; k++) {
                ins_min(v1s[tid * 16 + k], i1s[tid * 16 + k], bv1, bi1, bv2, bi2);
                ins_min(v2s[tid * 16 + k], i2s[tid * 16 + k], bv1, bi1, bv2, bi2);
            }
            g_meli1[grow] = bi1; g_meli2[grow] = bi2;
        }
    }
}

// ============================================================
// cast kernels
// ============================================================
__global__ void conv_bf16(const float4* __restrict__ in, uint2* __restrict__ out, int n4) {
    int i = blockIdx.x * blockDim.x + threadIdx.x;
    if (i < n4) {
        float4 v = in[i];
        __nv_bfloat162 a = __floats2bfloat162_rn(v.x, v.y);
        __nv_bfloat162 b = __floats2bfloat162_rn(v.z, v.w);
        uint2 u; u.x = *(uint32_t*)&a; u.y = *(uint32_t*)&b;
        out[i] = u;
    }
}

// hi = bf16(x); lo = bf16(x - hi)
__global__ void conv_split(const float4* __restrict__ in,
                           uint2* __restrict__ hi, uint2* __restrict__ lo, int n4) {
    int i = blockIdx.x * blockDim.x + threadIdx.x;
    if (i < n4) {
        float4 v = in[i];
        __nv_bfloat16 hx = __float2bfloat16_rn(v.x), hy = __float2bfloat16_rn(v.y);
        __nv_bfloat16 hz = __float2bfloat16_rn(v.z), hw = __float2bfloat16_rn(v.w);
        __nv_bfloat162 ha; ha.x = hx; ha.y = hy;
        __nv_bfloat162 hb; hb.x = hz; hb.y = hw;
        __nv_bfloat162 la = __floats2bfloat162_rn(v.x - __bfloat162float(hx), v.y - __bfloat162float(hy));
        __nv_bfloat162 lb = __floats2bfloat162_rn(v.z - __bfloat162float(hz), v.w - __bfloat162float(hw));
        uint2 uh; uh.x = *(uint32_t*)&ha; uh.y = *(uint32_t*)&hb;
        uint2 ul; ul.x = *(uint32_t*)&la; ul.y = *(uint32_t*)&lb;
        hi[i] = uh; lo[i] = ul;
    }
}

// ============================================================
// h kernel: H = leakyrelu(X*W1^T + b1) via 3x bf16-split
// (Ah*Bh + Ah*Bl + Al*Bh, fp32 accum; error ~2^-16 -> argmax-safe).
// CTA 128x256, k-chunk 64, 2-stage ring. Stage: Ah/Al 128rows + Bh/Bl 256rows.
// ============================================================
#define H_AL   (128 * BROWB)            // 18432
#define H_BH   (2 * 128 * BROWB)        // 36864
#define H_BL   (H_BH + 256 * BROWB)     // 73728
#define HSTAGE (H_BL + 256 * BROWB)     // 110592
#define SMEM_H (2 * HSTAGE)             // 221184

__device__ __forceinline__ void ld_chunk_h(char* sbase, int kb, int tid,
                                           const __nv_bfloat16* Ah, const __nv_bfloat16* Al,
                                           const __nv_bfloat16* Bh, const __nv_bfloat16* Bl)
{
    #pragma unroll
    for (int i = 0; i < 4; i++) {
        int f = tid + (i << 8);
        int r = f >> 3, c = f & 7;
        cp16(sbase +        r * BROWB + c * 16, Ah + (size_t)r * DIM + kb + c * 8);
        cp16(sbase + H_AL + r * BROWB + c * 16, Al + (size_t)r * DIM + kb + c * 8);
    }
    #pragma unroll
    for (int i = 0; i < 8; i++) {
        int f = tid + (i << 8);
        int r = f >> 3, c = f & 7;
        cp16(sbase + H_BH + r * BROWB + c * 16, Bh + (size_t)r * DIM + kb + c * 8);
        cp16(sbase + H_BL + r * BROWB + c * 16, Bl + (size_t)r * DIM + kb + c * 8);
    }
    CP_COMMIT();
}

__device__ __forceinline__ void compute_stage_h(const char* sbuf, float acc[4][8][4],
                                                int wm, int wn, int lane)
{
    const uint32_t sb = smem_u32(sbuf);
    const uint32_t aoff = (uint32_t)((wm * 64 + (lane & 7) + ((lane >> 3) & 1) * 8) * BROWB
                                     + ((lane >> 4) & 1) * 16);
    const uint32_t boff = (uint32_t)((wn * 64 + (lane & 7) + ((lane >> 4) & 1) * 8) * BROWB
                                     + ((lane >> 3) & 1) * 16);
    const uint32_t aH = sb + aoff, aL = sb + H_AL + aoff;
    const uint32_t bH = sb + H_BH + boff, bL = sb + H_BL + boff;
    #pragma unroll
    for (int k16 = 0; k16 < 4; k16++) {
        const uint32_t kb = (uint32_t)k16 * 32u;
        uint32_t ah[4][4], al[4][4], bh[8][2], bl[8][2];
        #pragma unroll
        for (int mi = 0; mi < 4; mi++) {
            ldsm4(ah[mi][0], ah[mi][1], ah[mi][2], ah[mi][3], aH + (uint32_t)mi * (16 * BROWB) + kb);
            ldsm4(al[mi][0], al[mi][1], al[mi][2], al[mi][3], aL + (uint32_t)mi * (16 * BROWB) + kb);
        }
        #pragma unroll
        for (int p = 0; p < 4; p++) {
            ldsm4(bh[2*p][0], bh[2*p][1], bh[2*p+1][0], bh[2*p+1][1], bH + (uint32_t)p * (16 * BROWB) + kb);
            ldsm4(bl[2*p][0], bl[2*p][1], bl[2*p+1][0], bl[2*p+1][1], bL + (uint32_t)p * (16 * BROWB) + kb);
        }
        #pragma unroll
        for (int mi = 0; mi < 4; mi++)
            #pragma unroll
            for (int ni = 0; ni < 8; ni++) {
                mma_bf16(acc[mi][ni], ah[mi], bh[ni]);
                mma_bf16(acc[mi][ni], ah[mi], bl[ni]);
                mma_bf16(acc[mi][ni], al[mi], bh[ni]);
            }
    }
}

__global__ void __launch_bounds__(256, 1)
h_mma_kernel(const float* __restrict__ b1)
{
    extern __shared__ float smf[];
    char* sm = (char*)smf;
    const int tid = threadIdx.x, w = tid >> 5, lane = tid & 31;
    const int wm = w >> 2, wn = w & 3, lr = lane >> 2, lq = lane & 3;
    const int row0 = blockIdx.x * MROWS;
    const int col0 = blockIdx.y * NROWS;
    const __nv_bfloat16* Ah = g_Xeh + (size_t)row0 * DIM;
    const __nv_bfloat16* Al = g_Xel + (size_t)row0 * DIM;
    const __nv_bfloat16* Bh = g_W1h + (size_t)col0 * DIM;
    const __nv_bfloat16* Bl = g_W1l + (size_t)col0 * DIM;

    float acc[4][8][4];
    #pragma unroll
    for (int mi = 0; mi < 4; mi++)
        #pragma unroll
        for (int ni = 0; ni < 8; ni++)
            #pragma unroll
            for (int j = 0; j < 4; j++) acc[mi][ni][j] = 0.f;

    ld_chunk_h(sm + 0 * HSTAGE, 0,  tid, Ah, Al, Bh, Bl);
    ld_chunk_h(sm + 1 * HSTAGE, 64, tid, Ah, Al, Bh, Bl);

    for (int kt = 0; kt < 8; kt++) {
        if (kt < 7) asm volatile("cp.async.wait_group 1;" ::: "memory");
        else        asm volatile("cp.async.wait_group 0;" ::: "memory");
        __syncthreads();
        compute_stage_h(sm + (kt & 1) * HSTAGE, acc, wm, wn, lane);
        if (kt + 2 < 8) {
            __syncthreads();   // all warps done with this buffer before reload
            ld_chunk_h(sm + (kt & 1) * HSTAGE, (kt + 2) * 64, tid, Ah, Al, Bh, Bl);
        }
    }

    #pragma unroll
    for (int mi = 0; mi < 4; mi++)
        #pragma unroll
        for (int h = 0; h < 2; h++) {
            int r = row0 + wm * 64 + mi * 16 + lr + h * 8;
            #pragma unroll
            for (int ni = 0; ni < 8; ni++) {
                int c = col0 + wn * 64 + ni * 8 + lq * 2;
                float x0 = acc[mi][ni][h * 2 + 0] + __ldg(&b1[c + 0]);
                float x1 = acc[mi][ni][h * 2 + 1] + __ldg(&b1[c + 1]);
                x0 = (x0 >= 0.f) ? x0 : NEG_SLOPE * x0;
                x1 = (x1 >= 0.f) ? x1 : NEG_SLOPE * x1;
                *(float2*)(g_H + (size_t)r * DIM + c) = make_float2(x0, x1);
                __nv_bfloat162 hb = __floats2bfloat162_rn(x0, x1);
                *(uint32_t*)(g_Hb + (size_t)r * DIM + c) = *(uint32_t*)&hb;
            }
        }
}

// ============================================================
// ||e_k||^2
// ============================================================
__global__ void esq_kernel(const float* __restrict__ E) {
    int row  = blockIdx.x * (blockDim.x >> 5) + (threadIdx.x >> 5);
    int lane = threadIdx.x & 31;
    const float* e = E + (size_t)row * DIM;
    float s = 0.f;
    for (int c = lane; c < DIM; c += 32) { float v = e[c]; s = fmaf(v, v, s); }
    #pragma unroll
    for (int o = 16; o; o >>= 1) s += __shfl_xor_sync(0xffffffffu, s, o);
    if (lane == 0) g_esq[row] = s;
}

// ============================================================
// fp32 refine: exact re-evaluation of top-2 candidates per row
// ============================================================
__device__ __forceinline__ float dot512(const float* __restrict__ a,
                                        const float* __restrict__ b, int lane)
{
    float s = 0.f;
    #pragma unroll
    for (int t = 0; t < 4; t++) {
        float4 x = *(const float4*)(a + (lane + 32 * t) * 4);
        float4 y = *(const float4*)(b + (lane + 32 * t) * 4);
        s = fmaf(x.x, y.x, s); s = fmaf(x.y, y.y, s);
        s = fmaf(x.z, y.z, s); s = fmaf(x.w, y.w, s);
    }
    #pragma unroll
    for (int o = 16; o; o >>= 1) s += __shfl_xor_sync(0xffffffffu, s, o);
    return s;
}

__global__ void __launch_bounds__(256)
refine_kernel(const float* __restrict__ Xmel, const float* __restrict__ E,
              const float* __restrict__ W2,  const float* __restrict__ b2)
{
    const int warp = threadIdx.x >> 5, lane = threadIdx.x & 31;
    const int row = blockIdx.x * 8 + warp;
    if (row >= BSZ) return;

    const float* xr = Xmel + (size_t)row * DIM;
    const float* hr = g_H  + (size_t)row * DIM;

    int mi1 = g_meli1[row], mi2 = g_meli2[row];
    float d1 = g_esq[mi1] - 2.f * dot512(xr, E + (size_t)mi1 * DIM, lane);
    float d2 = g_esq[mi2] - 2.f * dot512(xr, E + (size_t)mi2 * DIM, lane);
    int mel_idx = (d1 < d2 || (d1 == d2 && mi1 < mi2)) ? mi1 : mi2;

    int j1 = g_logi1[row], j2 = g_logi2[row];
    float l1 = dot512(hr, W2 + (size_t)j1 * DIM, lane) + b2[j1];
    float l2 = dot512(hr, W2 + (size_t)j2 * DIM, lane) + b2[j2];
    int eeg_idx = (l1 > l2 || (l1 == l2 && j1 < j2)) ? j1 : j2;

    float t = dot512(hr, W2 + (size_t)mel_idx * DIM, lane) + b2[mel_idx];

    if (lane == 0) {
        g_loss[row]  = g_lse[row] - t;
        g_match[row] = (eeg_idx == mel_idx) ? 1.f : 0.f;
    }
}

// ============================================================
// final mean reduction
// ============================================================
__global__ void reduce_kernel(float* __restrict__ out) {
    __shared__ float sl[1024];
    __shared__ float sa[1024];
    int tid = threadIdx.x;
    float a = 0.f, b = 0.f;
    for (int i = tid; i < BSZ; i += 1024) { a += g_loss[i]; b += g_match[i]; }
    sl[tid] = a; sa[tid] = b;
    __syncthreads();
    for (int o = 512; o; o >>= 1) {
        if (tid < o) { sl[tid] += sl[tid + o]; sa[tid] += sa[tid + o]; }
        __syncthreads();
    }
    if (tid == 0) {
        out[0] = sl[0] / (float)BSZ;
        out[1] = sa[0] / (float)BSZ;
    }
}

// ============================================================
extern "C" void kernel_launch(void* const* d_in, const int* in_sizes, int n_in,
                              void* d_out, int out_size)
{
    (void)in_sizes; (void)n_in; (void)out_size;
    const float* eeg = (const float*)d_in[0];
    const float* mel = (const float*)d_in[1];
    const float* emb = (const float*)d_in[2];
    const float* W1  = (const float*)d_in[3];
    const float* b1  = (const float*)d_in[4];
    const float* W2  = (const float*)d_in[5];
    const float* b2  = (const float*)d_in[6];
    float* out = (float*)d_out;

    cudaFuncSetAttribute(big_mma_all,  cudaFuncAttributeMaxDynamicSharedMemorySize, SMEM_BYTES);
    cudaFuncSetAttribute(h_mma_kernel, cudaFuncAttributeMaxDynamicSharedMemorySize, SMEM_H);

    __nv_bfloat16 *dEb, *dW2b, *dXmb, *dXeh, *dXel, *dW1h, *dW1l;
    cudaGetSymbolAddress((void**)&dEb,  g_Eb);
    cudaGetSymbolAddress((void**)&dW2b, g_W2b);
    cudaGetSymbolAddress((void**)&dXmb, g_Xmb);
    cudaGetSymbolAddress((void**)&dXeh, g_Xeh);
    cudaGetSymbolAddress((void**)&dXel, g_Xel);
    cudaGetSymbolAddress((void**)&dW1h, g_W1h);
    cudaGetSymbolAddress((void**)&dW1l, g_W1l);

    esq_kernel<<<KNUM / 8, 256>>>(emb);
    conv_bf16<<<(KNUM * DIM / 4 + 255) / 256, 256>>>((const float4*)emb, (uint2*)dEb,  KNUM * DIM / 4);
    conv_bf16<<<(KNUM * DIM / 4 + 255) / 256, 256>>>((const float4*)W2,  (uint2*)dW2b, KNUM * DIM / 4);
    conv_bf16<<<(BSZ * DIM / 4 + 255) / 256, 256>>>((const float4*)mel, (uint2*)dXmb, BSZ * DIM / 4);
    conv_split<<<(BSZ * DIM / 4 + 255) / 256, 256>>>((const float4*)eeg, (uint2*)dXeh, (uint2*)dXel, BSZ * DIM / 4);
    conv_split<<<(DIM * DIM / 4 + 255) / 256, 256>>>((const float4*)W1, (uint2*)dW1h, (uint2*)dW1l, DIM * DIM / 4);
    h_mma_kernel<<<dim3(BSZ / MROWS, DIM / NROWS), 256, SMEM_H>>>(b1);
    big_mma_all<<<256, 256, SMEM_BYTES>>>(dXmb, dEb, dW2b, b2);
    refine_kernel<<<BSZ / 8, 256>>>(mel, emb, W2, b2);
    reduce_kernel<<<1, 1024>>>(out);
}

// round 11
// speedup vs baseline: 2.2951x; 1.0986x over previous
#include <cuda_runtime.h>
#include <cuda_bf16.h>
#include <math.h>
#include <stdint.h>

#define BSZ   16384
#define DIM   512
#define KNUM  8192
#define NEG_SLOPE 0.01f

// ---- scratch (static device globals) ----
__device__ float g_esq[KNUM];
__device__ float g_H[(size_t)BSZ * DIM];            // fp32 hidden (exact, for refine)
__device__ __nv_bfloat16 g_Hb[(size_t)BSZ * DIM];   // bf16 hidden (GEMM input)
__device__ __nv_bfloat16 g_Eb[(size_t)KNUM * DIM];  // bf16 embeddings
__device__ __nv_bfloat16 g_W2b[(size_t)KNUM * DIM]; // bf16 W2
__device__ __nv_bfloat16 g_Xmb[(size_t)BSZ * DIM];  // bf16 mel input
__device__ __nv_bfloat16 g_Xeh[(size_t)BSZ * DIM];  // eeg hi/lo split
__device__ __nv_bfloat16 g_Xel[(size_t)BSZ * DIM];
__device__ __nv_bfloat16 g_W1h[(size_t)DIM * DIM];  // W1 hi/lo split
__device__ __nv_bfloat16 g_W1l[(size_t)DIM * DIM];
__device__ int   g_meli1[BSZ], g_meli2[BSZ];
__device__ int   g_logi1[BSZ], g_logi2[BSZ];
__device__ float g_lse[BSZ];
__device__ float g_loss[BSZ], g_match[BSZ];

// ============================================================
// common PTX helpers
// ============================================================
__device__ __forceinline__ uint32_t smem_u32(const void* p) {
    uint32_t a;
    asm("{ .reg .u64 t; cvta.to.shared.u64 t, %1; cvt.u32.u64 %0, t; }" : "=r"(a) : "l"(p));
    return a;
}
__device__ __forceinline__ void ldsm4(uint32_t& r0, uint32_t& r1, uint32_t& r2, uint32_t& r3,
                                      uint32_t addr) {
    asm volatile("ldmatrix.sync.aligned.m8n8.x4.shared.b16 {%0,%1,%2,%3}, [%4];"
                 : "=r"(r0), "=r"(r1), "=r"(r2), "=r"(r3) : "r"(addr));
}
__device__ __forceinline__ void cp16(void* dst, const void* src) {
    unsigned d = smem_u32(dst);
    asm volatile("cp.async.cg.shared.global [%0], [%1], 16;" :: "r"(d), "l"(src));
}
#define CP_COMMIT() asm volatile("cp.async.commit_group;" ::: "memory")

// bf16 m16n8k16
__device__ __forceinline__ void mma_bf16(float* d, const uint32_t* a, const uint32_t* b) {
    asm volatile(
        "mma.sync.aligned.m16n8k16.row.col.f32.bf16.bf16.f32 "
        "{%0,%1,%2,%3},{%4,%5,%6,%7},{%8,%9},{%0,%1,%2,%3};"
        : "+f"(d[0]), "+f"(d[1]), "+f"(d[2]), "+f"(d[3])
        : "r"(a[0]), "r"(a[1]), "r"(a[2]), "r"(a[3]), "r"(b[0]), "r"(b[1]));
}

// ============================================================
// big-GEMM (bf16): CTA tile 128(M) x 128(N-pass), k-chunk 64, 8 warps (4x2),
// warp tile 32x64, 3-stage cp.async ring. 2 CTAs/SM (occupancy-driven overlap).
// smem row = 144 B (128 B data + 16 pad) -> conflict-free ldmatrix.
// ============================================================
#define MROWS   128
#define NCOLS   128
#define BROWB   144
#define BSTAGE  ((MROWS + NCOLS) * BROWB)   // 36864 B
#define SMEM_BIG (3 * BSTAGE)               // 110592 B -> 2 CTAs/SM

// chunk loader: A[128][64] + B[128][64] bf16 -> one stage (256 threads, 8 cp16 each)
__device__ __forceinline__ void ld_chunk_bf(char* sbase,
                                            const __nv_bfloat16* Ag,
                                            const __nv_bfloat16* Bg,
                                            int kb, int tid)
{
    #pragma unroll
    for (int i = 0; i < 4; i++) {
        int f = tid + (i << 8);           // 0..1023
        int r = f >> 3, c = f & 7;        // A row 0..127
        cp16(sbase + r * BROWB + c * 16, Ag + (size_t)r * DIM + kb + c * 8);
    }
    #pragma unroll
    for (int i = 0; i < 4; i++) {
        int f = tid + (i << 8);
        int r = f >> 3, c = f & 7;        // B row 0..127
        cp16(sbase + (128 + r) * BROWB + c * 16, Bg + (size_t)r * DIM + kb + c * 8);
    }
    CP_COMMIT();
}

// 8-warp compute (4x2): warp tile 32x64, acc[2][8][4]
__device__ __forceinline__ void compute_stage_bf(const char* sbuf, float acc[2][8][4],
                                                 int wm, int wn, int lane)
{
    const uint32_t sb = smem_u32(sbuf);
    const uint32_t aAddr = sb + (uint32_t)((wm * 32 + (lane & 7) + ((lane >> 3) & 1) * 8) * BROWB
                                           + ((lane >> 4) & 1) * 16);
    const uint32_t bAddr = sb + (uint32_t)((128 + wn * 64 + (lane & 7) + ((lane >> 4) & 1) * 8) * BROWB
                                           + ((lane >> 3) & 1) * 16);
    #pragma unroll
    for (int k16 = 0; k16 < 4; k16++) {
        const uint32_t kb = (uint32_t)k16 * 32u;
        uint32_t a[2][4], b[8][2];
        #pragma unroll
        for (int mi = 0; mi < 2; mi++)
            ldsm4(a[mi][0], a[mi][1], a[mi][2], a[mi][3],
                  aAddr + (uint32_t)mi * (16 * BROWB) + kb);
        #pragma unroll
        for (int p = 0; p < 4; p++)
            ldsm4(b[2 * p][0], b[2 * p][1], b[2 * p + 1][0], b[2 * p + 1][1],
                  bAddr + (uint32_t)p * (16 * BROWB) + kb);
        #pragma unroll
        for (int mi = 0; mi < 2; mi++)
            #pragma unroll
            for (int ni = 0; ni < 8; ni++)
                mma_bf16(acc[mi][ni], a[mi], b[ni]);
    }
}

__device__ __forceinline__ void gemm_k512_bf(const __nv_bfloat16* Ag, const __nv_bfloat16* Bg,
                                             char* sm, float acc[2][8][4],
                                             int tid, int wm, int wn, int lane)
{
    #pragma unroll
    for (int mi = 0; mi < 2; mi++)
        #pragma unroll
        for (int ni = 0; ni < 8; ni++)
            #pragma unroll
            for (int j = 0; j < 4; j++) acc[mi][ni][j] = 0.f;

    __syncthreads();
    ld_chunk_bf(sm + 0 * BSTAGE, Ag, Bg, 0,  tid);
    ld_chunk_bf(sm + 1 * BSTAGE, Ag, Bg, 64, tid);

    for (int kt = 0; kt < 8; kt++) {
        if (kt < 7) asm volatile("cp.async.wait_group 1;" ::: "memory");
        else        asm volatile("cp.async.wait_group 0;" ::: "memory");
        __syncthreads();
        compute_stage_bf(sm + (kt % 3) * BSTAGE, acc, wm, wn, lane);
        if (kt + 2 < 8)
            ld_chunk_bf(sm + ((kt + 2) % 3) * BSTAGE, Ag, Bg, (kt + 2) * 64, tid);
    }
}

// top-2 insertion with index tiebreak + dedupe
__device__ __forceinline__ void ins_min(float v, int i, float& v1, int& i1, float& v2, int& i2) {
    if (v < v1 || (v == v1 && i < i1)) {
        if (i != i1) { v2 = v1; i2 = i1; }
        v1 = v; i1 = i;
    } else if (i != i1 && (v < v2 || (v == v2 && i < i2))) { v2 = v; i2 = i; }
}
__device__ __forceinline__ void ins_max(float v, int i, float& v1, int& i1, float& v2, int& i2) {
    if (v > v1 || (v == v1 && i < i1)) {
        if (i != i1) { v2 = v1; i2 = i1; }
        v1 = v; i1 = i;
    } else if (i != i1 && (v > v2 || (v == v2 && i < i2))) { v2 = v; i2 = i; }
}

// ============================================================
// MERGED big fused kernel: grid 256, 2 CTAs/SM.
// bx<128 -> mel argmin block bx; bx>=128 -> logits block bx-128 (reads g_Hb).
// ============================================================
__global__ void __launch_bounds__(256, 2)
big_mma_all(const __nv_bfloat16* __restrict__ Amel,
            const __nv_bfloat16* __restrict__ Bmel,
            const __nv_bfloat16* __restrict__ Blog,
            const float* __restrict__ b2)
{
    extern __shared__ float smf[];
    char* sm = (char*)smf;
    const int tid = threadIdx.x, w = tid >> 5, lane = tid & 31;
    const int wm = w >> 1, wn = w & 1, lr = lane >> 2, lq = lane & 3;
    const bool LOGITS = (blockIdx.x >= 128);
    const int row0 = (blockIdx.x & 127) * MROWS;
    const __nv_bfloat16* A = LOGITS ? (const __nv_bfloat16*)g_Hb : Amel;
    const __nv_bfloat16* B = LOGITS ? Blog : Bmel;
    const __nv_bfloat16* Ag = A + (size_t)row0 * DIM;

    float v1[4], v2[4], m[4], s[4]; int i1[4], i2[4];
    #pragma unroll
    for (int st = 0; st < 4; st++) {
        v1[st] = LOGITS ? -INFINITY : INFINITY; v2[st] = v1[st];
        i1[st] = 0x7fffffff; i2[st] = 0x7fffffff;
        m[st] = -INFINITY; s[st] = 0.f;
    }

    float acc[2][8][4];
    for (int nt = 0; nt < KNUM / NCOLS; nt++) {
        gemm_k512_bf(Ag, B + (size_t)nt * NCOLS * DIM, sm, acc, tid, wm, wn, lane);

        #pragma unroll
        for (int mi = 0; mi < 2; mi++)
            #pragma unroll
            for (int h = 0; h < 2; h++) {
                const int st = mi * 2 + h;
                if (LOGITS) {
                    float x16[16];
                    float mloc = -INFINITY;
                    #pragma unroll
                    for (int ni = 0; ni < 8; ni++)
                        #pragma unroll
                        for (int cc = 0; cc < 2; cc++) {
                            int col = nt * NCOLS + wn * 64 + ni * 8 + lq * 2 + cc;
                            float x = acc[mi][ni][h * 2 + cc] + __ldg(&b2[col]);
                            x16[ni * 2 + cc] = x;
                            mloc = fmaxf(mloc, x);
                            if (x > v1[st]) { v2[st] = v1[st]; i2[st] = i1[st]; v1[st] = x; i1[st] = col; }
                            else if (x > v2[st]) { v2[st] = x; i2[st] = col; }
                        }
                    float mn = fmaxf(m[st], mloc);
                    float ssum = 0.f;
                    #pragma unroll
                    for (int e = 0; e < 16; e++) ssum += __expf(x16[e] - mn);
                    s[st] = fmaf(s[st], __expf(m[st] - mn), ssum);
                    m[st] = mn;
                } else {
                    #pragma unroll
                    for (int ni = 0; ni < 8; ni++)
                        #pragma unroll
                        for (int cc = 0; cc < 2; cc++) {
                            int col = nt * NCOLS + wn * 64 + ni * 8 + lq * 2 + cc;
                            float d = fmaf(-2.f, acc[mi][ni][h * 2 + cc], __ldg(&g_esq[col]));
                            if (d < v1[st]) { v2[st] = v1[st]; i2[st] = i1[st]; v1[st] = d; i1[st] = col; }
                            else if (d < v2[st]) { v2[st] = d; i2[st] = col; }
                        }
                }
            }
    }

    // merge: 8 slots per row (wn x lq), rows 0..127
    __syncthreads();
    float* v1s = smf;                  float* v2s = smf + 1024;
    int*   i1s = (int*)(smf + 2048);   int*   i2s = (int*)(smf + 3072);
    float* ms  = smf + 4096;           float* ss  = smf + 5120;
    const int slot = wn * 4 + lq;
    #pragma unroll
    for (int mi = 0; mi < 2; mi++)
        #pragma unroll
        for (int h = 0; h < 2; h++) {
            int r  = wm * 32 + mi * 16 + lr + h * 8;
            int st = mi * 2 + h;
            v1s[r * 8 + slot] = v1[st]; v2s[r * 8 + slot] = v2[st];
            i1s[r * 8 + slot] = i1[st]; i2s[r * 8 + slot] = i2[st];
            if (LOGITS) { ms[r * 8 + slot] = m[st]; ss[r * 8 + slot] = s[st]; }
        }
    __syncthreads();
    if (tid < 128) {
        const int grow = row0 + tid;
        if (LOGITS) {
            float bv1 = -INFINITY, bv2 = -INFINITY; int bi1 = 0x7fffffff, bi2 = 0x7fffffff;
            float M = -INFINITY;
            #pragma unroll
            for (int k = 0; k < 8; k++) {
                ins_max(v1s[tid * 8 + k], i1s[tid * 8 + k], bv1, bi1, bv2, bi2);
                ins_max(v2s[tid * 8 + k], i2s[tid * 8 + k], bv1, bi1, bv2, bi2);
                M = fmaxf(M, ms[tid * 8 + k]);
            }
            float S = 0.f;
            #pragma unroll
            for (int k = 0; k < 8; k++) S += ss[tid * 8 + k] * __expf(ms[tid * 8 + k] - M);
            g_logi1[grow] = bi1; g_logi2[grow] = bi2;
            g_lse[grow]   = M + logf(S);
        } else {
            float bv1 = INFINITY, bv2 = INFINITY; int bi1 = 0x7fffffff, bi2 = 0x7fffffff;
            #pragma unroll
            for (int k = 0; k < 8; k++) {
                ins_min(v1s[tid * 8 + k], i1s[tid * 8 + k], bv1, bi1, bv2, bi2);
                ins_min(v2s[tid * 8 + k], i2s[tid * 8 + k], bv1, bi1, bv2, bi2);
            }
            g_meli1[grow] = bi1; g_meli2[grow] = bi2;
        }
    }
}

// ============================================================
// cast kernels
// ============================================================
__global__ void conv_bf16(const float4* __restrict__ in, uint2* __restrict__ out, int n4) {
    int i = blockIdx.x * blockDim.x + threadIdx.x;
    if (i < n4) {
        float4 v = in[i];
        __nv_bfloat162 a = __floats2bfloat162_rn(v.x, v.y);
        __nv_bfloat162 b = __floats2bfloat162_rn(v.z, v.w);
        uint2 u; u.x = *(uint32_t*)&a; u.y = *(uint32_t*)&b;
        out[i] = u;
    }
}

// hi = bf16(x); lo = bf16(x - hi)
__global__ void conv_split(const float4* __restrict__ in,
                           uint2* __restrict__ hi, uint2* __restrict__ lo, int n4) {
    int i = blockIdx.x * blockDim.x + threadIdx.x;
    if (i < n4) {
        float4 v = in[i];
        __nv_bfloat16 hx = __float2bfloat16_rn(v.x), hy = __float2bfloat16_rn(v.y);
        __nv_bfloat16 hz = __float2bfloat16_rn(v.z), hw = __float2bfloat16_rn(v.w);
        __nv_bfloat162 ha; ha.x = hx; ha.y = hy;
        __nv_bfloat162 hb; hb.x = hz; hb.y = hw;
        __nv_bfloat162 la = __floats2bfloat162_rn(v.x - __bfloat162float(hx), v.y - __bfloat162float(hy));
        __nv_bfloat162 lb = __floats2bfloat162_rn(v.z - __bfloat162float(hz), v.w - __bfloat162float(hw));
        uint2 uh; uh.x = *(uint32_t*)&ha; uh.y = *(uint32_t*)&hb;
        uint2 ul; ul.x = *(uint32_t*)&la; ul.y = *(uint32_t*)&lb;
        hi[i] = uh; lo[i] = ul;
    }
}

// ============================================================
// h kernel: H = leakyrelu(X*W1^T + b1) via 3x bf16-split
// (Ah*Bh + Ah*Bl + Al*Bh, fp32 accum; error ~2^-16 -> argmax-safe).
// CTA 128x256 (8 warps 2x4, warp tile 64x64), k-chunk 64, 2-stage ring.
// ============================================================
#define H_AL   (128 * BROWB)
#define H_BH   (2 * 128 * BROWB)
#define H_BL   (H_BH + 256 * BROWB)
#define HSTAGE (H_BL + 256 * BROWB)     // 110592
#define SMEM_H (2 * HSTAGE)             // 221184

__device__ __forceinline__ void ld_chunk_h(char* sbase, int kb, int tid,
                                           const __nv_bfloat16* Ah, const __nv_bfloat16* Al,
                                           const __nv_bfloat16* Bh, const __nv_bfloat16* Bl)
{
    #pragma unroll
    for (int i = 0; i < 4; i++) {
        int f = tid + (i << 8);
        int r = f >> 3, c = f & 7;
        cp16(sbase +        r * BROWB + c * 16, Ah + (size_t)r * DIM + kb + c * 8);
        cp16(sbase + H_AL + r * BROWB + c * 16, Al + (size_t)r * DIM + kb + c * 8);
    }
    #pragma unroll
    for (int i = 0; i < 8; i++) {
        int f = tid + (i << 8);
        int r = f >> 3, c = f & 7;
        cp16(sbase + H_BH + r * BROWB + c * 16, Bh + (size_t)r * DIM + kb + c * 8);
        cp16(sbase + H_BL + r * BROWB + c * 16, Bl + (size_t)r * DIM + kb + c * 8);
    }
    CP_COMMIT();
}

__device__ __forceinline__ void compute_stage_h(const char* sbuf, float acc[4][8][4],
                                                int wm, int wn, int lane)
{
    const uint32_t sb = smem_u32(sbuf);
    const uint32_t aoff = (uint32_t)((wm * 64 + (lane & 7) + ((lane >> 3) & 1) * 8) * BROWB
                                     + ((lane >> 4) & 1) * 16);
    const uint32_t boff = (uint32_t)((wn * 64 + (lane & 7) + ((lane >> 4) & 1) * 8) * BROWB
                                     + ((lane >> 3) & 1) * 16);
    const uint32_t aH = sb + aoff, aL = sb + H_AL + aoff;
    const uint32_t bH = sb + H_BH + boff, bL = sb + H_BL + boff;
    #pragma unroll
    for (int k16 = 0; k16 < 4; k16++) {
        const uint32_t kb = (uint32_t)k16 * 32u;
        uint32_t ah[4][4], al[4][4], bh[8][2], bl[8][2];
        #pragma unroll
        for (int mi = 0; mi < 4; mi++) {
            ldsm4(ah[mi][0], ah[mi][1], ah[mi][2], ah[mi][3], aH + (uint32_t)mi * (16 * BROWB) + kb);
            ldsm4(al[mi][0], al[mi][1], al[mi][2], al[mi][3], aL + (uint32_t)mi * (16 * BROWB) + kb);
        }
        #pragma unroll
        for (int p = 0; p < 4; p++) {
            ldsm4(bh[2*p][0], bh[2*p][1], bh[2*p+1][0], bh[2*p+1][1], bH + (uint32_t)p * (16 * BROWB) + kb);
            ldsm4(bl[2*p][0], bl[2*p][1], bl[2*p+1][0], bl[2*p+1][1], bL + (uint32_t)p * (16 * BROWB) + kb);
        }
        #pragma unroll
        for (int mi = 0; mi < 4; mi++)
            #pragma unroll
            for (int ni = 0; ni < 8; ni++) {
                mma_bf16(acc[mi][ni], ah[mi], bh[ni]);
                mma_bf16(acc[mi][ni], ah[mi], bl[ni]);
                mma_bf16(acc[mi][ni], al[mi], bh[ni]);
            }
    }
}

__global__ void __launch_bounds__(256, 1)
h_mma_kernel(const float* __restrict__ b1)
{
    extern __shared__ float smf[];
    char* sm = (char*)smf;
    const int tid = threadIdx.x, w = tid >> 5, lane = tid & 31;
    const int wm = w >> 2, wn = w & 3, lr = lane >> 2, lq = lane & 3;
    const int row0 = blockIdx.x * 128;
    const int col0 = blockIdx.y * 256;
    const __nv_bfloat16* Ah = g_Xeh + (size_t)row0 * DIM;
    const __nv_bfloat16* Al = g_Xel + (size_t)row0 * DIM;
    const __nv_bfloat16* Bh = g_W1h + (size_t)col0 * DIM;
    const __nv_bfloat16* Bl = g_W1l + (size_t)col0 * DIM;

    float acc[4][8][4];
    #pragma unroll
    for (int mi = 0; mi < 4; mi++)
        #pragma unroll
        for (int ni = 0; ni < 8; ni++)
            #pragma unroll
            for (int j = 0; j < 4; j++) acc[mi][ni][j] = 0.f;

    ld_chunk_h(sm + 0 * HSTAGE, 0,  tid, Ah, Al, Bh, Bl);
    ld_chunk_h(sm + 1 * HSTAGE, 64, tid, Ah, Al, Bh, Bl);

    for (int kt = 0; kt < 8; kt++) {
        if (kt < 7) asm volatile("cp.async.wait_group 1;" ::: "memory");
        else        asm volatile("cp.async.wait_group 0;" ::: "memory");
        __syncthreads();
        compute_stage_h(sm + (kt & 1) * HSTAGE, acc, wm, wn, lane);
        if (kt + 2 < 8) {
            __syncthreads();
            ld_chunk_h(sm + (kt & 1) * HSTAGE, (kt + 2) * 64, tid, Ah, Al, Bh, Bl);
        }
    }

    #pragma unroll
    for (int mi = 0; mi < 4; mi++)
        #pragma unroll
        for (int h = 0; h < 2; h++) {
            int r = row0 + wm * 64 + mi * 16 + lr + h * 8;
            #pragma unroll
            for (int ni = 0; ni < 8; ni++) {
                int c = col0 + wn * 64 + ni * 8 + lq * 2;
                float x0 = acc[mi][ni][h * 2 + 0] + __ldg(&b1[c + 0]);
                float x1 = acc[mi][ni][h * 2 + 1] + __ldg(&b1[c + 1]);
                x0 = (x0 >= 0.f) ? x0 : NEG_SLOPE * x0;
                x1 = (x1 >= 0.f) ? x1 : NEG_SLOPE * x1;
                *(float2*)(g_H + (size_t)r * DIM + c) = make_float2(x0, x1);
                __nv_bfloat162 hb = __floats2bfloat162_rn(x0, x1);
                *(uint32_t*)(g_Hb + (size_t)r * DIM + c) = *(uint32_t*)&hb;
            }
        }
}

// ============================================================
// ||e_k||^2
// ============================================================
__global__ void esq_kernel(const float* __restrict__ E) {
    int row  = blockIdx.x * (blockDim.x >> 5) + (threadIdx.x >> 5);
    int lane = threadIdx.x & 31;
    const float* e = E + (size_t)row * DIM;
    float s = 0.f;
    for (int c = lane; c < DIM; c += 32) { float v = e[c]; s = fmaf(v, v, s); }
    #pragma unroll
    for (int o = 16; o; o >>= 1) s += __shfl_xor_sync(0xffffffffu, s, o);
    if (lane == 0) g_esq[row] = s;
}

// ============================================================
// fp32 refine: exact re-evaluation of top-2 candidates per row
// ============================================================
__device__ __forceinline__ float dot512(const float* __restrict__ a,
                                        const float* __restrict__ b, int lane)
{
    float s = 0.f;
    #pragma unroll
    for (int t = 0; t < 4; t++) {
        float4 x = *(const float4*)(a + (lane + 32 * t) * 4);
        float4 y = *(const float4*)(b + (lane + 32 * t) * 4);
        s = fmaf(x.x, y.x, s); s = fmaf(x.y, y.y, s);
        s = fmaf(x.z, y.z, s); s = fmaf(x.w, y.w, s);
    }
    #pragma unroll
    for (int o = 16; o; o >>= 1) s += __shfl_xor_sync(0xffffffffu, s, o);
    return s;
}

__global__ void __launch_bounds__(256)
refine_kernel(const float* __restrict__ Xmel, const float* __restrict__ E,
              const float* __restrict__ W2,  const float* __restrict__ b2)
{
    const int warp = threadIdx.x >> 5, lane = threadIdx.x & 31;
    const int row = blockIdx.x * 8 + warp;
    if (row >= BSZ) return;

    const float* xr = Xmel + (size_t)row * DIM;
    const float* hr = g_H  + (size_t)row * DIM;

    int mi1 = g_meli1[row], mi2 = g_meli2[row];
    float d1 = g_esq[mi1] - 2.f * dot512(xr, E + (size_t)mi1 * DIM, lane);
    float d2 = g_esq[mi2] - 2.f * dot512(xr, E + (size_t)mi2 * DIM, lane);
    int mel_idx = (d1 < d2 || (d1 == d2 && mi1 < mi2)) ? mi1 : mi2;

    int j1 = g_logi1[row], j2 = g_logi2[row];
    float l1 = dot512(hr, W2 + (size_t)j1 * DIM, lane) + b2[j1];
    float l2 = dot512(hr, W2 + (size_t)j2 * DIM, lane) + b2[j2];
    int eeg_idx = (l1 > l2 || (l1 == l2 && j1 < j2)) ? j1 : j2;

    float t = dot512(hr, W2 + (size_t)mel_idx * DIM, lane) + b2[mel_idx];

    if (lane == 0) {
        g_loss[row]  = g_lse[row] - t;
        g_match[row] = (eeg_idx == mel_idx) ? 1.f : 0.f;
    }
}

// ============================================================
// final mean reduction
// ============================================================
__global__ void reduce_kernel(float* __restrict__ out) {
    __shared__ float sl[1024];
    __shared__ float sa[1024];
    int tid = threadIdx.x;
    float a = 0.f, b = 0.f;
    for (int i = tid; i < BSZ; i += 1024) { a += g_loss[i]; b += g_match[i]; }
    sl[tid] = a; sa[tid] = b;
    __syncthreads();
    for (int o = 512; o; o >>= 1) {
        if (tid < o) { sl[tid] += sl[tid + o]; sa[tid] += sa[tid + o]; }
        __syncthreads();
    }
    if (tid == 0) {
        out[0] = sl[0] / (float)BSZ;
        out[1] = sa[0] / (float)BSZ;
    }
}

// ============================================================
extern "C" void kernel_launch(void* const* d_in, const int* in_sizes, int n_in,
                              void* d_out, int out_size)
{
    (void)in_sizes; (void)n_in; (void)out_size;
    const float* eeg = (const float*)d_in[0];
    const float* mel = (const float*)d_in[1];
    const float* emb = (const float*)d_in[2];
    const float* W1  = (const float*)d_in[3];
    const float* b1  = (const float*)d_in[4];
    const float* W2  = (const float*)d_in[5];
    const float* b2  = (const float*)d_in[6];
    float* out = (float*)d_out;

    cudaFuncSetAttribute(big_mma_all,  cudaFuncAttributeMaxDynamicSharedMemorySize, SMEM_BIG);
    cudaFuncSetAttribute(h_mma_kernel, cudaFuncAttributeMaxDynamicSharedMemorySize, SMEM_H);

    __nv_bfloat16 *dEb, *dW2b, *dXmb, *dXeh, *dXel, *dW1h, *dW1l;
    cudaGetSymbolAddress((void**)&dEb,  g_Eb);
    cudaGetSymbolAddress((void**)&dW2b, g_W2b);
    cudaGetSymbolAddress((void**)&dXmb, g_Xmb);
    cudaGetSymbolAddress((void**)&dXeh, g_Xeh);
    cudaGetSymbolAddress((void**)&dXel, g_Xel);
    cudaGetSymbolAddress((void**)&dW1h, g_W1h);
    cudaGetSymbolAddress((void**)&dW1l, g_W1l);

    esq_kernel<<<KNUM / 8, 256>>>(emb);
    conv_bf16<<<(KNUM * DIM / 4 + 255) / 256, 256>>>((const float4*)emb, (uint2*)dEb,  KNUM * DIM / 4);
    conv_bf16<<<(KNUM * DIM / 4 + 255) / 256, 256>>>((const float4*)W2,  (uint2*)dW2b, KNUM * DIM / 4);
    conv_bf16<<<(BSZ * DIM / 4 + 255) / 256, 256>>>((const float4*)mel, (uint2*)dXmb, BSZ * DIM / 4);
    conv_split<<<(BSZ * DIM / 4 + 255) / 256, 256>>>((const float4*)eeg, (uint2*)dXeh, (uint2*)dXel, BSZ * DIM / 4);
    conv_split<<<(DIM * DIM / 4 + 255) / 256, 256>>>((const float4*)W1, (uint2*)dW1h, (uint2*)dW1l, DIM * DIM / 4);
    h_mma_kernel<<<dim3(BSZ / 128, DIM / 256), 256, SMEM_H>>>(b1);
    big_mma_all<<<256, 256, SMEM_BIG>>>(dXmb, dEb, dW2b, b2);
    refine_kernel<<<BSZ / 8, 256>>>(mel, emb, W2, b2);
    reduce_kernel<<<1, 1024>>>(out);
}